// round 8
// baseline (speedup 1.0000x reference)
#include <cuda_runtime.h>
#include <cuda_fp16.h>
#include <cstdint>

#define B_  8
#define H_  8
#define NQ_ 1024
#define NKV_ 2048
#define D_  512
#define HD_ 64

// ---------------- scratch (static __device__, no allocs) ----------------
__device__ __half g_Qh [B_ * H_ * NQ_  * HD_];   // [b][h][q][hd]   8 MB
__device__ __half g_Kh [B_ * H_ * NKV_ * HD_];   // [b][h][kv][hd] 16 MB
__device__ __half g_Vh [B_ * H_ * NKV_ * HD_];   // [b][h][kv][hd] 16 MB
__device__ float  g_AO [B_ * NQ_ * D_];          // [b][q][d]      16 MB (fp32)

// ---------------- helpers ----------------
__device__ __forceinline__ uint32_t smem_u32(const void* p) {
    uint32_t a;
    asm("{ .reg .u64 t; cvta.to.shared.u64 t, %1; cvt.u32.u64 %0, t; }" : "=r"(a) : "l"(p));
    return a;
}
__device__ __forceinline__ void cp16s(uint32_t d, const void* src) {
    asm volatile("cp.async.cg.shared.global [%0], [%1], 16;" :: "r"(d), "l"(src));
}
#define CP_COMMIT() asm volatile("cp.async.commit_group;")

__device__ __forceinline__ void mma_f16(float* c, const uint32_t* a, uint32_t b0, uint32_t b1) {
    asm volatile(
        "mma.sync.aligned.m16n8k16.row.col.f32.f16.f16.f32 "
        "{%0,%1,%2,%3}, {%4,%5,%6,%7}, {%8,%9}, {%0,%1,%2,%3};"
        : "+f"(c[0]), "+f"(c[1]), "+f"(c[2]), "+f"(c[3])
        : "r"(a[0]), "r"(a[1]), "r"(a[2]), "r"(a[3]), "r"(b0), "r"(b1));
}
__device__ __forceinline__ void ldsm4(uint32_t* r, uint32_t addr) {
    asm volatile("ldmatrix.sync.aligned.m8n8.x4.shared.b16 {%0,%1,%2,%3}, [%4];"
                 : "=r"(r[0]), "=r"(r[1]), "=r"(r[2]), "=r"(r[3]) : "r"(addr));
}
__device__ __forceinline__ void ldsm4t(uint32_t* r, uint32_t addr) {
    asm volatile("ldmatrix.sync.aligned.m8n8.x4.trans.shared.b16 {%0,%1,%2,%3}, [%4];"
                 : "=r"(r[0]), "=r"(r[1]), "=r"(r[2]), "=r"(r[3]) : "r"(addr));
}
__device__ __forceinline__ uint32_t h2pack(float a, float b) {
    __half2 h = __floats2half2_rn(a, b);
    return *(uint32_t*)&h;
}

// =======================================================================
// fp16 GEMM: out[m][n] = sum_k A[m][k] * W[n][k]   (M x 512 @ 512 x 512)
// DST 0: g_Qh, 1: g_Kh, 2: g_Vh (natural [b][h][seq][hd] half)
// DST 3: fp32 out, A = g_AO (fp32, converted during smem staging).
// =======================================================================
#define GSTB 80
#define GEMM_SMEM (4 * 128 * GSTB)          // A0 A1 W0 W1 = 40960 B

template<int DST>
__global__ __launch_bounds__(256, 2)
void gemm_f16(const float* __restrict__ A, const float* __restrict__ W,
              float* __restrict__ out_param, int M, int Nseq)
{
    extern __shared__ char smem[];
    const uint32_t sb = smem_u32(smem);
    const uint32_t AO[2] = { 0u, 10240u };
    const uint32_t WO[2] = { 20480u, 30720u };

    const int tid  = threadIdx.x;
    const int lane = tid & 31;
    const int wid  = tid >> 5;
    const int wm   = wid >> 2;
    const int wn   = wid & 3;
    const int m0   = blockIdx.y * 128;
    const int n0   = blockIdx.x * 128;

    const uint32_t a_l = (uint32_t)(lane & 15) * GSTB + (uint32_t)(lane >> 4) * 16;
    const uint32_t b_l = (uint32_t)((lane & 7) + ((lane >> 4) & 1) * 8) * GSTB
                       + (uint32_t)((lane >> 3) & 1) * 16;

    float acc[4][4][4];
    #pragma unroll
    for (int i = 0; i < 4; i++)
        #pragma unroll
        for (int j = 0; j < 4; j++)
            #pragma unroll
            for (int r = 0; r < 4; r++) acc[i][j][r] = 0.f;

    const float* Ae = (DST == 3) ? (const float*)g_AO : A;
    const float* Wg = W + (size_t)n0 * 512;

    float4 ar[2][2]; float4 wr[2][2];

    auto ldg = [&](int kt) {
        #pragma unroll
        for (int i = 0; i < 2; i++) {
            int idx = tid + i * 256;
            int row = idx >> 2, kg = (idx & 3) * 8;
            const float* p = Ae + (size_t)(m0 + row) * 512 + kt * 32 + kg;
            ar[i][0] = *(const float4*)p;
            ar[i][1] = *(const float4*)(p + 4);
            const float* q = Wg + (size_t)row * 512 + kt * 32 + kg;
            wr[i][0] = *(const float4*)q;
            wr[i][1] = *(const float4*)(q + 4);
        }
    };
    auto sts = [&](int buf) {
        #pragma unroll
        for (int i = 0; i < 2; i++) {
            int idx = tid + i * 256;
            int row = idx >> 2, kg = (idx & 3) * 8;
            __half2 ha[4] = {
                __floats2half2_rn(ar[i][0].x, ar[i][0].y),
                __floats2half2_rn(ar[i][0].z, ar[i][0].w),
                __floats2half2_rn(ar[i][1].x, ar[i][1].y),
                __floats2half2_rn(ar[i][1].z, ar[i][1].w) };
            *(uint4*)(smem + AO[buf] + (size_t)row * GSTB + kg * 2) = *(uint4*)ha;
            __half2 hw[4] = {
                __floats2half2_rn(wr[i][0].x, wr[i][0].y),
                __floats2half2_rn(wr[i][0].z, wr[i][0].w),
                __floats2half2_rn(wr[i][1].x, wr[i][1].y),
                __floats2half2_rn(wr[i][1].z, wr[i][1].w) };
            *(uint4*)(smem + WO[buf] + (size_t)row * GSTB + kg * 2) = *(uint4*)hw;
        }
    };

    ldg(0);
    sts(0);
    __syncthreads();

    for (int kt = 0; kt < 16; kt++) {
        const int buf = kt & 1;
        if (kt < 15) ldg(kt + 1);

        const uint32_t Ab = sb + AO[buf] + (uint32_t)(wm * 64) * GSTB + a_l;
        const uint32_t Wb = sb + WO[buf] + (uint32_t)(wn * 32) * GSTB + b_l;
        #pragma unroll
        for (int ks = 0; ks < 2; ks++) {
            uint32_t bm[2][4];
            #pragma unroll
            for (int nb = 0; nb < 2; nb++)
                ldsm4(bm[nb], Wb + (uint32_t)(nb * 16) * GSTB + ks * 32);
            #pragma unroll
            for (int ma = 0; ma < 4; ma++) {
                uint32_t a[4];
                ldsm4(a, Ab + (uint32_t)(ma * 16) * GSTB + ks * 32);
                #pragma unroll
                for (int nb = 0; nb < 2; nb++) {
                    mma_f16(acc[ma][nb * 2],     a, bm[nb][0], bm[nb][1]);
                    mma_f16(acc[ma][nb * 2 + 1], a, bm[nb][2], bm[nb][3]);
                }
            }
        }
        if (kt < 15) {
            sts(buf ^ 1);
            __syncthreads();
        }
    }

    // epilogue
    __half* dsth = (DST == 0) ? g_Qh : (DST == 1) ? g_Kh : g_Vh;
    #pragma unroll
    for (int ma = 0; ma < 4; ma++) {
        #pragma unroll
        for (int na = 0; na < 4; na++) {
            const int m = m0 + wm * 64 + ma * 16 + (lane >> 2);
            const int n = n0 + wn * 32 + na * 8 + 2 * (lane & 3);
            const float* a = acc[ma][na];
            if (DST != 3) {
                const int bb = m / Nseq;
                const int nn = m - bb * Nseq;
                const int h  = n >> 6;
                const int hd = n & 63;
                __half* base = dsth + (((size_t)bb * H_ + h) * Nseq + nn) * HD_ + hd;
                *(__half2*)base              = __floats2half2_rn(a[0], a[1]);
                *(__half2*)(base + 8 * HD_)  = __floats2half2_rn(a[2], a[3]);
            } else {
                *(float2*)(out_param + (size_t)m * 512 + n)       = make_float2(a[0], a[1]);
                *(float2*)(out_param + (size_t)(m + 8) * 512 + n) = make_float2(a[2], a[3]);
            }
        }
    }
}

// =======================================================================
// fp16 flash attention, additive bias, online softmax.
// 4-STAGE cp.async pipeline, ONE __syncthreads per tile.
// Bias for tile t+1 prefetched into registers after P pack (s[] dead).
// Conditional O rescale (skipped when no row max changed, warp-uniform).
// =======================================================================
#define ASTB 144
#define KVST (2 * 64 * ASTB)                        // K+V per stage = 18432
#define ATT_SMEM (128 * ASTB + 4 * KVST)            // 92160 B

__global__ __launch_bounds__(256, 2)
void attn_f16(const float* __restrict__ pos_bias)
{
    extern __shared__ char smem[];
    const uint32_t sb  = smem_u32(smem);
    const uint32_t SQ  = sb;
    const uint32_t SKV = sb + 128 * ASTB;           // stage s: K at +s*KVST, V at +s*KVST+9216

    const int tid  = threadIdx.x;
    const int lane = tid & 31;
    const int wid  = tid >> 5;
    const int bx = blockIdx.x;
    const int qt = bx & 7;
    const int h  = (bx >> 3) & 7;
    const int b  = bx >> 6;
    const int mrow = wid * 16;

    const uint32_t q_l = (uint32_t)(mrow + (lane & 15)) * ASTB + (uint32_t)(lane >> 4) * 16;
    const uint32_t k_l = (uint32_t)((lane & 7) + ((lane >> 4) & 1) * 8) * ASTB
                       + (uint32_t)((lane >> 3) & 1) * 16;
    const uint32_t v_l = (uint32_t)((lane & 7) + ((lane >> 3) & 1) * 8) * ASTB
                       + (uint32_t)((lane >> 4) & 1) * 16;

    const __half* Qg  = g_Qh + (((size_t)b * H_ + h) * NQ_ + (size_t)qt * 128) * HD_;
    const __half* Kg0 = g_Kh + (((size_t)b * H_ + h) * NKV_) * HD_;
    const __half* Vg0 = g_Vh + (((size_t)b * H_ + h) * NKV_) * HD_;

    // load K+V for tile tt into stage st (512 x 16B each)
    auto load_kv = [&](int tt, int st) {
        const uint32_t SK = SKV + (uint32_t)st * KVST;
        const uint32_t SV = SK + 9216;
        const __half* Kg = Kg0 + (size_t)tt * 64 * HD_;
        const __half* Vg = Vg0 + (size_t)tt * 64 * HD_;
        #pragma unroll
        for (int i = 0; i < 2; i++) {
            int idx = tid + i * 256, r = idx >> 3, s = idx & 7;
            cp16s(SK + (uint32_t)r * ASTB + s * 16, Kg + (size_t)r * HD_ + s * 8);
            cp16s(SV + (uint32_t)r * ASTB + s * 16, Vg + (size_t)r * HD_ + s * 8);
        }
    };

    // prologue: group 0 = Q + tile0, group 1 = tile1, group 2 = tile2
    #pragma unroll
    for (int i = 0; i < 4; i++) {
        int idx = tid + i * 256, r = idx >> 3, s = idx & 7;
        cp16s(SQ + (uint32_t)r * ASTB + s * 16, Qg + (size_t)r * HD_ + s * 8);
    }
    load_kv(0, 0); CP_COMMIT();
    load_kv(1, 1); CP_COMMIT();
    load_kv(2, 2); CP_COMMIT();

    float o[8][4];
    #pragma unroll
    for (int na = 0; na < 8; na++)
        #pragma unroll
        for (int r = 0; r < 4; r++) o[na][r] = 0.f;
    float m_0 = -1e30f, m_1 = -1e30f, l0 = 0.f, l1 = 0.f;

    const float* bias_r0 = pos_bias
        + ((size_t)h * NQ_ + (size_t)qt * 128 + mrow + (lane >> 2)) * NKV_ + 2 * (lane & 3);

    // bias for tile 0 preloaded
    float2 blo[8], bhi[8];
    #pragma unroll
    for (int na = 0; na < 8; na++) {
        blo[na] = *(const float2*)(bias_r0 + na * 8);
        bhi[na] = *(const float2*)(bias_r0 + (size_t)8 * NKV_ + na * 8);
    }

    for (int t = 0; t < 32; t++) {
        const uint32_t K = SKV + (uint32_t)(t & 3) * KVST;
        const uint32_t V = K + 9216;

        asm volatile("cp.async.wait_group 2;");
        __syncthreads();

        // prefetch tile t+3 into stage (t+3)&3 (safe: that slot was last
        // read at iter t-1, and the barrier above drained iter t-1)
        if (t + 3 < 32) load_kv(t + 3, (t + 3) & 3);
        CP_COMMIT();   // always commit (possibly empty) to keep group count aligned

        // ---- S = Q @ K^T ----
        float s[8][4];
        #pragma unroll
        for (int na = 0; na < 8; na++)
            #pragma unroll
            for (int r = 0; r < 4; r++) s[na][r] = 0.f;

        #pragma unroll
        for (int ks = 0; ks < 4; ks++) {
            uint32_t a[4];
            ldsm4(a, SQ + q_l + ks * 32);
            #pragma unroll
            for (int nb = 0; nb < 4; nb++) {
                uint32_t bm[4];
                ldsm4(bm, K + k_l + (uint32_t)(nb * 16) * ASTB + ks * 32);
                mma_f16(s[nb * 2],     a, bm[0], bm[1]);
                mma_f16(s[nb * 2 + 1], a, bm[2], bm[3]);
            }
        }

        // ---- + bias (preloaded registers) ----
        #pragma unroll
        for (int na = 0; na < 8; na++) {
            s[na][0] += blo[na].x; s[na][1] += blo[na].y;
            s[na][2] += bhi[na].x; s[na][3] += bhi[na].y;
        }

        // ---- online softmax ----
        float rmax0 = -1e30f, rmax1 = -1e30f;
        #pragma unroll
        for (int na = 0; na < 8; na++) {
            rmax0 = fmaxf(rmax0, fmaxf(s[na][0], s[na][1]));
            rmax1 = fmaxf(rmax1, fmaxf(s[na][2], s[na][3]));
        }
        rmax0 = fmaxf(rmax0, __shfl_xor_sync(0xffffffffu, rmax0, 1));
        rmax0 = fmaxf(rmax0, __shfl_xor_sync(0xffffffffu, rmax0, 2));
        rmax1 = fmaxf(rmax1, __shfl_xor_sync(0xffffffffu, rmax1, 1));
        rmax1 = fmaxf(rmax1, __shfl_xor_sync(0xffffffffu, rmax1, 2));

        const float mn0 = fmaxf(m_0, rmax0);
        const float mn1 = fmaxf(m_1, rmax1);
        const float al0 = __expf(m_0 - mn0);
        const float al1 = __expf(m_1 - mn1);
        m_0 = mn0; m_1 = mn1;

        float rs0 = 0.f, rs1 = 0.f;
        #pragma unroll
        for (int na = 0; na < 8; na++) {
            s[na][0] = __expf(s[na][0] - mn0); rs0 += s[na][0];
            s[na][1] = __expf(s[na][1] - mn0); rs0 += s[na][1];
            s[na][2] = __expf(s[na][2] - mn1); rs1 += s[na][2];
            s[na][3] = __expf(s[na][3] - mn1); rs1 += s[na][3];
        }
        l0 = l0 * al0 + rs0;
        l1 = l1 * al1 + rs1;

        // ---- pack P (s dead afterwards) ----
        uint32_t pp[4][4];
        #pragma unroll
        for (int ks = 0; ks < 4; ks++) {
            pp[ks][0] = h2pack(s[2*ks][0],   s[2*ks][1]);
            pp[ks][1] = h2pack(s[2*ks][2],   s[2*ks][3]);
            pp[ks][2] = h2pack(s[2*ks+1][0], s[2*ks+1][1]);
            pp[ks][3] = h2pack(s[2*ks+1][2], s[2*ks+1][3]);
        }

        // ---- prefetch bias for t+1 (hides LDG under PV + next QK) ----
        if (t < 31) {
            const float* bb = bias_r0 + (size_t)(t + 1) * 64;
            #pragma unroll
            for (int na = 0; na < 8; na++) {
                blo[na] = *(const float2*)(bb + na * 8);
                bhi[na] = *(const float2*)(bb + (size_t)8 * NKV_ + na * 8);
            }
        }

        // ---- conditional O rescale ----
        bool need = (al0 != 1.0f) || (al1 != 1.0f);
        if (__any_sync(0xffffffffu, need)) {
            #pragma unroll
            for (int na = 0; na < 8; na++) {
                o[na][0] *= al0; o[na][1] *= al0;
                o[na][2] *= al1; o[na][3] *= al1;
            }
        }

        // ---- O += P @ V ----
        #pragma unroll
        for (int ks = 0; ks < 4; ks++) {
            #pragma unroll
            for (int nb = 0; nb < 4; nb++) {
                uint32_t bm[4];
                ldsm4t(bm, V + v_l + (uint32_t)(ks * 16) * ASTB + nb * 32);
                mma_f16(o[nb * 2],     pp[ks], bm[0], bm[1]);
                mma_f16(o[nb * 2 + 1], pp[ks], bm[2], bm[3]);
            }
        }
    }

    // ---- finalize ----
    l0 += __shfl_xor_sync(0xffffffffu, l0, 1);
    l0 += __shfl_xor_sync(0xffffffffu, l0, 2);
    l1 += __shfl_xor_sync(0xffffffffu, l1, 1);
    l1 += __shfl_xor_sync(0xffffffffu, l1, 2);
    const float inv0 = 1.0f / l0;
    const float inv1 = 1.0f / l1;

    const size_t r0 = (size_t)b * NQ_ + (size_t)qt * 128 + mrow + (lane >> 2);
    #pragma unroll
    for (int na = 0; na < 8; na++) {
        const int col = h * HD_ + na * 8 + 2 * (lane & 3);
        *(float2*)(g_AO + r0 * D_ + col) =
            make_float2(o[na][0] * inv0, o[na][1] * inv0);
        *(float2*)(g_AO + (r0 + 8) * D_ + col) =
            make_float2(o[na][2] * inv1, o[na][3] * inv1);
    }
}

// =======================================================================
// launch
// =======================================================================
extern "C" void kernel_launch(void* const* d_in, const int* in_sizes, int n_in,
                              void* d_out, int out_size)
{
    const float* x        = (const float*)d_in[0];
    const float* enc      = (const float*)d_in[1];
    const float* pos_bias = (const float*)d_in[2];
    const float* Wq       = (const float*)d_in[3];
    const float* Wk       = (const float*)d_in[4];
    const float* Wv       = (const float*)d_in[5];
    const float* Wo       = (const float*)d_in[6];
    float* out = (float*)d_out;

    cudaFuncSetAttribute(gemm_f16<0>, cudaFuncAttributeMaxDynamicSharedMemorySize, GEMM_SMEM);
    cudaFuncSetAttribute(gemm_f16<1>, cudaFuncAttributeMaxDynamicSharedMemorySize, GEMM_SMEM);
    cudaFuncSetAttribute(gemm_f16<2>, cudaFuncAttributeMaxDynamicSharedMemorySize, GEMM_SMEM);
    cudaFuncSetAttribute(gemm_f16<3>, cudaFuncAttributeMaxDynamicSharedMemorySize, GEMM_SMEM);
    cudaFuncSetAttribute(attn_f16,    cudaFuncAttributeMaxDynamicSharedMemorySize, ATT_SMEM);

    gemm_f16<0><<<dim3(4, 64),  256, GEMM_SMEM>>>(x,   Wq, nullptr, B_ * NQ_,  NQ_);
    gemm_f16<1><<<dim3(4, 128), 256, GEMM_SMEM>>>(enc, Wk, nullptr, B_ * NKV_, NKV_);
    gemm_f16<2><<<dim3(4, 128), 256, GEMM_SMEM>>>(enc, Wv, nullptr, B_ * NKV_, NKV_);
    attn_f16<<<B_ * H_ * (NQ_ / 128), 256, ATT_SMEM>>>(pos_bias);
    gemm_f16<3><<<dim3(4, 64), 256, GEMM_SMEM>>>(nullptr, Wo, out, B_ * NQ_, NQ_);
}

// round 12
// speedup vs baseline: 1.0128x; 1.0128x over previous
#include <cuda_runtime.h>
#include <cuda_fp16.h>
#include <cstdint>

#define B_  8
#define H_  8
#define NQ_ 1024
#define NKV_ 2048
#define D_  512
#define HD_ 64

// ---------------- scratch (56 MB, identical to R8) ----------------------
// NOTE: these symbols are referenced ONLY from device code. Passing a
// __device__ symbol as a kernel argument from host code produced the
// 128MiB resource violations in R9/R10.
__device__ __half g_Qh [B_ * H_ * NQ_  * HD_];   //  8 MB
__device__ __half g_Kh [B_ * H_ * NKV_ * HD_];   // 16 MB
__device__ __half g_Vh [B_ * H_ * NKV_ * HD_];   // 16 MB; first 8MB doubles as x_fp16
__device__ float  g_AO [B_ * NQ_ * D_];          // 16 MB; doubles as enc_fp16

// ---------------- helpers ----------------
__device__ __forceinline__ uint32_t smem_u32(const void* p) {
    uint32_t a;
    asm("{ .reg .u64 t; cvta.to.shared.u64 t, %1; cvt.u32.u64 %0, t; }" : "=r"(a) : "l"(p));
    return a;
}
__device__ __forceinline__ void cp16s(uint32_t d, const void* src) {
    asm volatile("cp.async.cg.shared.global [%0], [%1], 16;" :: "r"(d), "l"(src));
}
#define CP_COMMIT() asm volatile("cp.async.commit_group;")

__device__ __forceinline__ void mma_f16(float* c, const uint32_t* a, uint32_t b0, uint32_t b1) {
    asm volatile(
        "mma.sync.aligned.m16n8k16.row.col.f32.f16.f16.f32 "
        "{%0,%1,%2,%3}, {%4,%5,%6,%7}, {%8,%9}, {%0,%1,%2,%3};"
        : "+f"(c[0]), "+f"(c[1]), "+f"(c[2]), "+f"(c[3])
        : "r"(a[0]), "r"(a[1]), "r"(a[2]), "r"(a[3]), "r"(b0), "r"(b1));
}
__device__ __forceinline__ void ldsm4(uint32_t* r, uint32_t addr) {
    asm volatile("ldmatrix.sync.aligned.m8n8.x4.shared.b16 {%0,%1,%2,%3}, [%4];"
                 : "=r"(r[0]), "=r"(r[1]), "=r"(r[2]), "=r"(r[3]) : "r"(addr));
}
__device__ __forceinline__ void ldsm4t(uint32_t* r, uint32_t addr) {
    asm volatile("ldmatrix.sync.aligned.m8n8.x4.trans.shared.b16 {%0,%1,%2,%3}, [%4];"
                 : "=r"(r[0]), "=r"(r[1]), "=r"(r[2]), "=r"(r[3]) : "r"(addr));
}
__device__ __forceinline__ uint32_t h2pack(float a, float b) {
    __half2 h = __floats2half2_rn(a, b);
    return *(uint32_t*)&h;
}

// =======================================================================
// fp32 -> fp16 convert. WHICH 0: dst = g_Vh bytes (x), 1: dst = g_AO
// bytes (enc). Destination resolved DEVICE-SIDE.
// =======================================================================
template<int WHICH>
__global__ __launch_bounds__(256)
void cvt_h(const float* __restrict__ s, int n)
{
    __half* d = (WHICH == 0) ? (__half*)g_Vh : (__half*)g_AO;
    int i = (blockIdx.x * 256 + threadIdx.x) * 8;
    if (i >= n) return;
    float4 a = *(const float4*)(s + i);
    float4 b = *(const float4*)(s + i + 4);
    __half2 h[4] = { __floats2half2_rn(a.x, a.y), __floats2half2_rn(a.z, a.w),
                     __floats2half2_rn(b.x, b.y), __floats2half2_rn(b.z, b.w) };
    *(uint4*)(d + i) = *(uint4*)h;
}

// =======================================================================
// Hybrid projection GEMM: A fp16 (aliased scratch, resolved device-side)
// via 3-stage cp.async; W fp32 reg-staged+cvt double buffer. BK=64.
// out[m][n] = sum_k A[m][k] * W[n][k]; head-split fp16 epilogue.
// DST 0: A = g_Vh bytes (x_fp16)  -> g_Qh
// DST 1: A = g_AO bytes (enc_fp16)-> g_Kh
// DST 2: A = g_AO bytes (enc_fp16)-> g_Vh
// =======================================================================
#define GSTB 144
#define GTILE (128 * GSTB)                     // 18432 B
#define GEMM_SMEM (3 * GTILE + 2 * GTILE)      // A x3 + W x2 = 92160 B

template<int DST>
__global__ __launch_bounds__(256, 2)
void gemm_h(const float* __restrict__ W, int Nseq)
{
    extern __shared__ char smem[];
    const uint32_t sb = smem_u32(smem);
    const uint32_t WB = sb + 3 * GTILE;

    const int tid  = threadIdx.x;
    const int lane = tid & 31;
    const int wid  = tid >> 5;
    const int wm   = wid >> 2;
    const int wn   = wid & 3;
    const int m0   = blockIdx.y * 128;
    const int n0   = blockIdx.x * 128;

    const __half* A = (DST == 0) ? (const __half*)g_Vh : (const __half*)g_AO;

    const uint32_t a_l = (uint32_t)(lane & 15) * GSTB + (uint32_t)(lane >> 4) * 16;
    const uint32_t b_l = (uint32_t)((lane & 7) + ((lane >> 4) & 1) * 8) * GSTB
                       + (uint32_t)((lane >> 3) & 1) * 16;

    float acc[4][4][4];
    #pragma unroll
    for (int i = 0; i < 4; i++)
        #pragma unroll
        for (int j = 0; j < 4; j++)
            #pragma unroll
            for (int r = 0; r < 4; r++) acc[i][j][r] = 0.f;

    const __half* Ag = A + (size_t)m0 * 512;
    const float*  Wg = W + (size_t)n0 * 512;

    auto load_a = [&](int kt, int st) {
        const uint32_t SA = sb + (uint32_t)st * GTILE;
        #pragma unroll
        for (int i = 0; i < 4; i++) {
            int idx = tid + i * 256;
            int r = idx >> 3, sg = idx & 7;
            cp16s(SA + (uint32_t)r * GSTB + sg * 16,
                  Ag + (size_t)r * 512 + kt * 64 + sg * 8);
        }
    };

    float4 wr[4][2];
    auto ldg_w = [&](int kt) {
        #pragma unroll
        for (int i = 0; i < 4; i++) {
            int idx = tid + i * 256;
            int r = idx >> 3, sg = idx & 7;
            const float* q = Wg + (size_t)r * 512 + kt * 64 + sg * 8;
            wr[i][0] = *(const float4*)q;
            wr[i][1] = *(const float4*)(q + 4);
        }
    };
    auto sts_w = [&](int buf) {
        #pragma unroll
        for (int i = 0; i < 4; i++) {
            int idx = tid + i * 256;
            int r = idx >> 3, sg = idx & 7;
            __half2 hw[4] = {
                __floats2half2_rn(wr[i][0].x, wr[i][0].y),
                __floats2half2_rn(wr[i][0].z, wr[i][0].w),
                __floats2half2_rn(wr[i][1].x, wr[i][1].y),
                __floats2half2_rn(wr[i][1].z, wr[i][1].w) };
            *(uint4*)(smem + 3 * GTILE + buf * GTILE + (size_t)r * GSTB + sg * 16) = *(uint4*)hw;
        }
    };

    // prologue
    load_a(0, 0); CP_COMMIT();
    load_a(1, 1); CP_COMMIT();
    ldg_w(0);
    sts_w(0);
    __syncthreads();

    for (int kt = 0; kt < 8; kt++) {
        const int st = kt % 3;
        if (kt + 2 < 8) load_a(kt + 2, (kt + 2) % 3);
        CP_COMMIT();
        asm volatile("cp.async.wait_group 2;");   // A(kt) arrived

        if (kt < 7) ldg_w(kt + 1);                // LDG hidden under MMAs

        const uint32_t Ab = sb + (uint32_t)st * GTILE + (uint32_t)(wm * 64) * GSTB + a_l;
        const uint32_t Wb = WB + (uint32_t)(kt & 1) * GTILE + (uint32_t)(wn * 32) * GSTB + b_l;
        #pragma unroll
        for (int ks = 0; ks < 4; ks++) {
            uint32_t bm[2][4];
            ldsm4(bm[0], Wb + ks * 32);
            ldsm4(bm[1], Wb + (uint32_t)16 * GSTB + ks * 32);
            #pragma unroll
            for (int ma = 0; ma < 4; ma++) {
                uint32_t a[4];
                ldsm4(a, Ab + (uint32_t)(ma * 16) * GSTB + ks * 32);
                #pragma unroll
                for (int nb = 0; nb < 2; nb++) {
                    mma_f16(acc[ma][nb * 2],     a, bm[nb][0], bm[nb][1]);
                    mma_f16(acc[ma][nb * 2 + 1], a, bm[nb][2], bm[nb][3]);
                }
            }
        }
        if (kt < 7) sts_w((kt + 1) & 1);
        __syncthreads();
    }

    // epilogue: head-split fp16
    __half* dsth = (DST == 0) ? g_Qh : (DST == 1) ? g_Kh : g_Vh;
    #pragma unroll
    for (int ma = 0; ma < 4; ma++) {
        #pragma unroll
        for (int na = 0; na < 4; na++) {
            const int m = m0 + wm * 64 + ma * 16 + (lane >> 2);
            const int n = n0 + wn * 32 + na * 8 + 2 * (lane & 3);
            const float* a = acc[ma][na];
            const int bb = m / Nseq;
            const int nn = m - bb * Nseq;
            const int h  = n >> 6;
            const int hd = n & 63;
            __half* base = dsth + (((size_t)bb * H_ + h) * Nseq + nn) * HD_ + hd;
            *(__half2*)base              = __floats2half2_rn(a[0], a[1]);
            *(__half2*)(base + 8 * HD_)  = __floats2half2_rn(a[2], a[3]);
        }
    }
}

// =======================================================================
// Wo GEMM (R8-proven): A = g_AO fp32 reg-staged, W fp32 reg-staged,
// fp32 output. BK=32, double buffer.
// =======================================================================
#define WSTB 80
#define WO_SMEM (4 * 128 * WSTB)               // 40960 B

__global__ __launch_bounds__(256, 2)
void gemm_wo(const float* __restrict__ W, float* __restrict__ out)
{
    extern __shared__ char smem[];
    const uint32_t sb = smem_u32(smem);
    const uint32_t AO2[2] = { 0u, 10240u };
    const uint32_t WO2[2] = { 20480u, 30720u };

    const int tid  = threadIdx.x;
    const int lane = tid & 31;
    const int wid  = tid >> 5;
    const int wm   = wid >> 2;
    const int wn   = wid & 3;
    const int m0   = blockIdx.y * 128;
    const int n0   = blockIdx.x * 128;

    const uint32_t a_l = (uint32_t)(lane & 15) * WSTB + (uint32_t)(lane >> 4) * 16;
    const uint32_t b_l = (uint32_t)((lane & 7) + ((lane >> 4) & 1) * 8) * WSTB
                       + (uint32_t)((lane >> 3) & 1) * 16;

    float acc[4][4][4];
    #pragma unroll
    for (int i = 0; i < 4; i++)
        #pragma unroll
        for (int j = 0; j < 4; j++)
            #pragma unroll
            for (int r = 0; r < 4; r++) acc[i][j][r] = 0.f;

    const float* Ae = g_AO;
    const float* Wg = W + (size_t)n0 * 512;

    float4 ar[2][2]; float4 wr[2][2];

    auto ldg = [&](int kt) {
        #pragma unroll
        for (int i = 0; i < 2; i++) {
            int idx = tid + i * 256;
            int row = idx >> 2, kg = (idx & 3) * 8;
            const float* p = Ae + (size_t)(m0 + row) * 512 + kt * 32 + kg;
            ar[i][0] = *(const float4*)p;
            ar[i][1] = *(const float4*)(p + 4);
            const float* q = Wg + (size_t)row * 512 + kt * 32 + kg;
            wr[i][0] = *(const float4*)q;
            wr[i][1] = *(const float4*)(q + 4);
        }
    };
    auto sts = [&](int buf) {
        #pragma unroll
        for (int i = 0; i < 2; i++) {
            int idx = tid + i * 256;
            int row = idx >> 2, kg = (idx & 3) * 8;
            __half2 ha[4] = {
                __floats2half2_rn(ar[i][0].x, ar[i][0].y),
                __floats2half2_rn(ar[i][0].z, ar[i][0].w),
                __floats2half2_rn(ar[i][1].x, ar[i][1].y),
                __floats2half2_rn(ar[i][1].z, ar[i][1].w) };
            *(uint4*)(smem + AO2[buf] + (size_t)row * WSTB + kg * 2) = *(uint4*)ha;
            __half2 hw[4] = {
                __floats2half2_rn(wr[i][0].x, wr[i][0].y),
                __floats2half2_rn(wr[i][0].z, wr[i][0].w),
                __floats2half2_rn(wr[i][1].x, wr[i][1].y),
                __floats2half2_rn(wr[i][1].z, wr[i][1].w) };
            *(uint4*)(smem + WO2[buf] + (size_t)row * WSTB + kg * 2) = *(uint4*)hw;
        }
    };

    ldg(0);
    sts(0);
    __syncthreads();

    for (int kt = 0; kt < 16; kt++) {
        const int buf = kt & 1;
        if (kt < 15) ldg(kt + 1);

        const uint32_t Ab = sb + AO2[buf] + (uint32_t)(wm * 64) * WSTB + a_l;
        const uint32_t Wb = sb + WO2[buf] + (uint32_t)(wn * 32) * WSTB + b_l;
        #pragma unroll
        for (int ks = 0; ks < 2; ks++) {
            uint32_t bm[2][4];
            #pragma unroll
            for (int nb = 0; nb < 2; nb++)
                ldsm4(bm[nb], Wb + (uint32_t)(nb * 16) * WSTB + ks * 32);
            #pragma unroll
            for (int ma = 0; ma < 4; ma++) {
                uint32_t a[4];
                ldsm4(a, Ab + (uint32_t)(ma * 16) * WSTB + ks * 32);
                #pragma unroll
                for (int nb = 0; nb < 2; nb++) {
                    mma_f16(acc[ma][nb * 2],     a, bm[nb][0], bm[nb][1]);
                    mma_f16(acc[ma][nb * 2 + 1], a, bm[nb][2], bm[nb][3]);
                }
            }
        }
        if (kt < 15) {
            sts(buf ^ 1);
            __syncthreads();
        }
    }

    #pragma unroll
    for (int ma = 0; ma < 4; ma++) {
        #pragma unroll
        for (int na = 0; na < 4; na++) {
            const int m = m0 + wm * 64 + ma * 16 + (lane >> 2);
            const int n = n0 + wn * 32 + na * 8 + 2 * (lane & 3);
            const float* a = acc[ma][na];
            *(float2*)(out + (size_t)m * 512 + n)       = make_float2(a[0], a[1]);
            *(float2*)(out + (size_t)(m + 8) * 512 + n) = make_float2(a[2], a[3]);
        }
    }
}

// =======================================================================
// fp16 flash attention — R8 kernel unchanged (203 us).
// =======================================================================
#define ASTB 144
#define KVST (2 * 64 * ASTB)
#define ATT_SMEM (128 * ASTB + 4 * KVST)      // 92160 B

__global__ __launch_bounds__(256, 2)
void attn_f16(const float* __restrict__ pos_bias)
{
    extern __shared__ char smem[];
    const uint32_t sb  = smem_u32(smem);
    const uint32_t SQ  = sb;
    const uint32_t SKV = sb + 128 * ASTB;

    const int tid  = threadIdx.x;
    const int lane = tid & 31;
    const int wid  = tid >> 5;
    const int bx = blockIdx.x;
    const int qt = bx & 7;
    const int h  = (bx >> 3) & 7;
    const int b  = bx >> 6;
    const int mrow = wid * 16;

    const uint32_t q_l = (uint32_t)(mrow + (lane & 15)) * ASTB + (uint32_t)(lane >> 4) * 16;
    const uint32_t k_l = (uint32_t)((lane & 7) + ((lane >> 4) & 1) * 8) * ASTB
                       + (uint32_t)((lane >> 3) & 1) * 16;
    const uint32_t v_l = (uint32_t)((lane & 7) + ((lane >> 3) & 1) * 8) * ASTB
                       + (uint32_t)((lane >> 4) & 1) * 16;

    const __half* Qg  = g_Qh + (((size_t)b * H_ + h) * NQ_ + (size_t)qt * 128) * HD_;
    const __half* Kg0 = g_Kh + (((size_t)b * H_ + h) * NKV_) * HD_;
    const __half* Vg0 = g_Vh + (((size_t)b * H_ + h) * NKV_) * HD_;

    auto load_kv = [&](int tt, int st) {
        const uint32_t SK = SKV + (uint32_t)st * KVST;
        const uint32_t SV = SK + 9216;
        const __half* Kg = Kg0 + (size_t)tt * 64 * HD_;
        const __half* Vg = Vg0 + (size_t)tt * 64 * HD_;
        #pragma unroll
        for (int i = 0; i < 2; i++) {
            int idx = tid + i * 256, r = idx >> 3, s = idx & 7;
            cp16s(SK + (uint32_t)r * ASTB + s * 16, Kg + (size_t)r * HD_ + s * 8);
            cp16s(SV + (uint32_t)r * ASTB + s * 16, Vg + (size_t)r * HD_ + s * 8);
        }
    };

    #pragma unroll
    for (int i = 0; i < 4; i++) {
        int idx = tid + i * 256, r = idx >> 3, s = idx & 7;
        cp16s(SQ + (uint32_t)r * ASTB + s * 16, Qg + (size_t)r * HD_ + s * 8);
    }
    load_kv(0, 0); CP_COMMIT();
    load_kv(1, 1); CP_COMMIT();
    load_kv(2, 2); CP_COMMIT();

    float o[8][4];
    #pragma unroll
    for (int na = 0; na < 8; na++)
        #pragma unroll
        for (int r = 0; r < 4; r++) o[na][r] = 0.f;
    float m_0 = -1e30f, m_1 = -1e30f, l0 = 0.f, l1 = 0.f;

    const float* bias_r0 = pos_bias
        + ((size_t)h * NQ_ + (size_t)qt * 128 + mrow + (lane >> 2)) * NKV_ + 2 * (lane & 3);

    float2 blo[8], bhi[8];
    #pragma unroll
    for (int na = 0; na < 8; na++) {
        blo[na] = *(const float2*)(bias_r0 + na * 8);
        bhi[na] = *(const float2*)(bias_r0 + (size_t)8 * NKV_ + na * 8);
    }

    for (int t = 0; t < 32; t++) {
        const uint32_t K = SKV + (uint32_t)(t & 3) * KVST;
        const uint32_t V = K + 9216;

        asm volatile("cp.async.wait_group 2;");
        __syncthreads();

        if (t + 3 < 32) load_kv(t + 3, (t + 3) & 3);
        CP_COMMIT();

        float s[8][4];
        #pragma unroll
        for (int na = 0; na < 8; na++)
            #pragma unroll
            for (int r = 0; r < 4; r++) s[na][r] = 0.f;

        #pragma unroll
        for (int ks = 0; ks < 4; ks++) {
            uint32_t a[4];
            ldsm4(a, SQ + q_l + ks * 32);
            #pragma unroll
            for (int nb = 0; nb < 4; nb++) {
                uint32_t bm[4];
                ldsm4(bm, K + k_l + (uint32_t)(nb * 16) * ASTB + ks * 32);
                mma_f16(s[nb * 2],     a, bm[0], bm[1]);
                mma_f16(s[nb * 2 + 1], a, bm[2], bm[3]);
            }
        }

        #pragma unroll
        for (int na = 0; na < 8; na++) {
            s[na][0] += blo[na].x; s[na][1] += blo[na].y;
            s[na][2] += bhi[na].x; s[na][3] += bhi[na].y;
        }

        float rmax0 = -1e30f, rmax1 = -1e30f;
        #pragma unroll
        for (int na = 0; na < 8; na++) {
            rmax0 = fmaxf(rmax0, fmaxf(s[na][0], s[na][1]));
            rmax1 = fmaxf(rmax1, fmaxf(s[na][2], s[na][3]));
        }
        rmax0 = fmaxf(rmax0, __shfl_xor_sync(0xffffffffu, rmax0, 1));
        rmax0 = fmaxf(rmax0, __shfl_xor_sync(0xffffffffu, rmax0, 2));
        rmax1 = fmaxf(rmax1, __shfl_xor_sync(0xffffffffu, rmax1, 1));
        rmax1 = fmaxf(rmax1, __shfl_xor_sync(0xffffffffu, rmax1, 2));

        const float mn0 = fmaxf(m_0, rmax0);
        const float mn1 = fmaxf(m_1, rmax1);
        const float al0 = __expf(m_0 - mn0);
        const float al1 = __expf(m_1 - mn1);
        m_0 = mn0; m_1 = mn1;

        float rs0 = 0.f, rs1 = 0.f;
        #pragma unroll
        for (int na = 0; na < 8; na++) {
            s[na][0] = __expf(s[na][0] - mn0); rs0 += s[na][0];
            s[na][1] = __expf(s[na][1] - mn0); rs0 += s[na][1];
            s[na][2] = __expf(s[na][2] - mn1); rs1 += s[na][2];
            s[na][3] = __expf(s[na][3] - mn1); rs1 += s[na][3];
        }
        l0 = l0 * al0 + rs0;
        l1 = l1 * al1 + rs1;

        uint32_t pp[4][4];
        #pragma unroll
        for (int ks = 0; ks < 4; ks++) {
            pp[ks][0] = h2pack(s[2*ks][0],   s[2*ks][1]);
            pp[ks][1] = h2pack(s[2*ks][2],   s[2*ks][3]);
            pp[ks][2] = h2pack(s[2*ks+1][0], s[2*ks+1][1]);
            pp[ks][3] = h2pack(s[2*ks+1][2], s[2*ks+1][3]);
        }

        if (t < 31) {
            const float* bb = bias_r0 + (size_t)(t + 1) * 64;
            #pragma unroll
            for (int na = 0; na < 8; na++) {
                blo[na] = *(const float2*)(bb + na * 8);
                bhi[na] = *(const float2*)(bb + (size_t)8 * NKV_ + na * 8);
            }
        }

        bool need = (al0 != 1.0f) || (al1 != 1.0f);
        if (__any_sync(0xffffffffu, need)) {
            #pragma unroll
            for (int na = 0; na < 8; na++) {
                o[na][0] *= al0; o[na][1] *= al0;
                o[na][2] *= al1; o[na][3] *= al1;
            }
        }

        #pragma unroll
        for (int ks = 0; ks < 4; ks++) {
            #pragma unroll
            for (int nb = 0; nb < 4; nb++) {
                uint32_t bm[4];
                ldsm4t(bm, V + v_l + (uint32_t)(ks * 16) * ASTB + nb * 32);
                mma_f16(o[nb * 2],     pp[ks], bm[0], bm[1]);
                mma_f16(o[nb * 2 + 1], pp[ks], bm[2], bm[3]);
            }
        }
    }

    l0 += __shfl_xor_sync(0xffffffffu, l0, 1);
    l0 += __shfl_xor_sync(0xffffffffu, l0, 2);
    l1 += __shfl_xor_sync(0xffffffffu, l1, 1);
    l1 += __shfl_xor_sync(0xffffffffu, l1, 2);
    const float inv0 = 1.0f / l0;
    const float inv1 = 1.0f / l1;

    const size_t r0 = (size_t)b * NQ_ + (size_t)qt * 128 + mrow + (lane >> 2);
    #pragma unroll
    for (int na = 0; na < 8; na++) {
        const int col = h * HD_ + na * 8 + 2 * (lane & 3);
        *(float2*)(g_AO + r0 * D_ + col) =
            make_float2(o[na][0] * inv0, o[na][1] * inv0);
        *(float2*)(g_AO + (r0 + 8) * D_ + col) =
            make_float2(o[na][2] * inv1, o[na][3] * inv1);
    }
}

// =======================================================================
// launch — only d_in pointers cross host->device. Aliasing via stream
// order: x_fp16 in g_Vh (consumed by Q proj before V proj overwrites);
// enc_fp16 in g_AO (consumed by K/V proj before attention overwrites).
// =======================================================================
extern "C" void kernel_launch(void* const* d_in, const int* in_sizes, int n_in,
                              void* d_out, int out_size)
{
    const float* x        = (const float*)d_in[0];
    const float* enc      = (const float*)d_in[1];
    const float* pos_bias = (const float*)d_in[2];
    const float* Wq       = (const float*)d_in[3];
    const float* Wk       = (const float*)d_in[4];
    const float* Wv       = (const float*)d_in[5];
    const float* Wo       = (const float*)d_in[6];
    float* out = (float*)d_out;

    cudaFuncSetAttribute(gemm_h<0>, cudaFuncAttributeMaxDynamicSharedMemorySize, GEMM_SMEM);
    cudaFuncSetAttribute(gemm_h<1>, cudaFuncAttributeMaxDynamicSharedMemorySize, GEMM_SMEM);
    cudaFuncSetAttribute(gemm_h<2>, cudaFuncAttributeMaxDynamicSharedMemorySize, GEMM_SMEM);
    cudaFuncSetAttribute(gemm_wo,   cudaFuncAttributeMaxDynamicSharedMemorySize, WO_SMEM);
    cudaFuncSetAttribute(attn_f16,  cudaFuncAttributeMaxDynamicSharedMemorySize, ATT_SMEM);

    const int NX = B_ * NQ_ * D_;          // 4M elements
    const int NE = B_ * NKV_ * D_;         // 8M elements
    cvt_h<0><<<NX / 2048, 256>>>(x,   NX);
    cvt_h<1><<<NE / 2048, 256>>>(enc, NE);

    // projections (A = fp16 aliased scratch via cp.async; W = fp32 reg-staged)
    gemm_h<0><<<dim3(4, 64),  256, GEMM_SMEM>>>(Wq, NQ_);
    gemm_h<1><<<dim3(4, 128), 256, GEMM_SMEM>>>(Wk, NKV_);
    gemm_h<2><<<dim3(4, 128), 256, GEMM_SMEM>>>(Wv, NKV_);
    // attention (overwrites g_AO with fp32 AO)
    attn_f16<<<B_ * H_ * (NQ_ / 128), 256, ATT_SMEM>>>(pos_bias);
    // output projection
    gemm_wo<<<dim3(4, 64), 256, WO_SMEM>>>(Wo, out);
}

// round 13
// speedup vs baseline: 1.1366x; 1.1222x over previous
#include <cuda_runtime.h>
#include <cuda_fp16.h>
#include <cstdint>

#define B_  8
#define H_  8
#define NQ_ 1024
#define NKV_ 2048
#define D_  512
#define HD_ 64

// ---------------- scratch (56 MB, unchanged) ----------------------------
// Symbols referenced ONLY from device code (host-side decay of __device__
// symbols caused the R9/R10 resource violations).
__device__ __half g_Qh [B_ * H_ * NQ_  * HD_];   //  8 MB
__device__ __half g_Kh [B_ * H_ * NKV_ * HD_];   // 16 MB
__device__ __half g_Vh [B_ * H_ * NKV_ * HD_];   // 16 MB; first 8MB doubles as x_fp16
__device__ float  g_AO [B_ * NQ_ * D_];          // 16 MB; doubles as enc_fp16

// ---------------- helpers ----------------
__device__ __forceinline__ uint32_t smem_u32(const void* p) {
    uint32_t a;
    asm("{ .reg .u64 t; cvta.to.shared.u64 t, %1; cvt.u32.u64 %0, t; }" : "=r"(a) : "l"(p));
    return a;
}
__device__ __forceinline__ void cp16s(uint32_t d, const void* src) {
    asm volatile("cp.async.cg.shared.global [%0], [%1], 16;" :: "r"(d), "l"(src));
}
#define CP_COMMIT() asm volatile("cp.async.commit_group;")

__device__ __forceinline__ void mma_f16(float* c, const uint32_t* a, uint32_t b0, uint32_t b1) {
    asm volatile(
        "mma.sync.aligned.m16n8k16.row.col.f32.f16.f16.f32 "
        "{%0,%1,%2,%3}, {%4,%5,%6,%7}, {%8,%9}, {%0,%1,%2,%3};"
        : "+f"(c[0]), "+f"(c[1]), "+f"(c[2]), "+f"(c[3])
        : "r"(a[0]), "r"(a[1]), "r"(a[2]), "r"(a[3]), "r"(b0), "r"(b1));
}
__device__ __forceinline__ void ldsm4(uint32_t* r, uint32_t addr) {
    asm volatile("ldmatrix.sync.aligned.m8n8.x4.shared.b16 {%0,%1,%2,%3}, [%4];"
                 : "=r"(r[0]), "=r"(r[1]), "=r"(r[2]), "=r"(r[3]) : "r"(addr));
}
__device__ __forceinline__ void ldsm4t(uint32_t* r, uint32_t addr) {
    asm volatile("ldmatrix.sync.aligned.m8n8.x4.trans.shared.b16 {%0,%1,%2,%3}, [%4];"
                 : "=r"(r[0]), "=r"(r[1]), "=r"(r[2]), "=r"(r[3]) : "r"(addr));
}
__device__ __forceinline__ uint32_t h2pack(float a, float b) {
    __half2 h = __floats2half2_rn(a, b);
    return *(uint32_t*)&h;
}

// =======================================================================
// Fused fp32->fp16 convert: x -> g_Vh bytes, enc -> g_AO bytes,
// Wq/Wk/Wv -> wh (= d_out scratch, legal until gemm_wo overwrites).
// =======================================================================
#define NX_ (B_ * NQ_ * D_)        // 4194304
#define NE_ (B_ * NKV_ * D_)       // 8388608
#define NW_ (D_ * D_)              // 262144
#define CVT_TOTAL (NX_ + NE_ + 3 * NW_)

__device__ __forceinline__ void cvt8(const float* __restrict__ s, __half* __restrict__ d, int i) {
    float4 a = *(const float4*)(s + i);
    float4 b = *(const float4*)(s + i + 4);
    __half2 h[4] = { __floats2half2_rn(a.x, a.y), __floats2half2_rn(a.z, a.w),
                     __floats2half2_rn(b.x, b.y), __floats2half2_rn(b.z, b.w) };
    *(uint4*)(d + i) = *(uint4*)h;
}

__global__ __launch_bounds__(256)
void cvt_all(const float* __restrict__ x, const float* __restrict__ enc,
             const float* __restrict__ wq, const float* __restrict__ wk,
             const float* __restrict__ wv, __half* __restrict__ wh)
{
    int i = (blockIdx.x * 256 + threadIdx.x) * 8;
    if (i < NX_) {
        cvt8(x, (__half*)g_Vh, i);
    } else if (i < NX_ + NE_) {
        cvt8(enc, (__half*)g_AO, i - NX_);
    } else if (i < NX_ + NE_ + NW_) {
        cvt8(wq, wh, i - NX_ - NE_);
    } else if (i < NX_ + NE_ + 2 * NW_) {
        cvt8(wk, wh + NW_, i - NX_ - NE_ - NW_);
    } else if (i < CVT_TOTAL) {
        cvt8(wv, wh + 2 * NW_, i - NX_ - NE_ - 2 * NW_);
    }
}

// =======================================================================
// Fused QKV projection: pure-fp16 GEMM, both operands via 3-stage
// cp.async. BK=64, tile 128x128. Inner loop = ldsm + mma only.
// blockIdx.z: 0 -> Q (A = x_fp16 in g_Vh, M=8192), 1 -> K, 2 -> V
// (A = enc_fp16 in g_AO, M=16384). W = wh + z*NW_ (fp16 in d_out scratch).
// =======================================================================
#define GSTB 144
#define GTILE (128 * GSTB)                   // 18432 B
#define GSTG  (2 * GTILE)                    // A+W per stage = 36864 B
#define GEMM_SMEM (3 * GSTG)                 // 110592 B

__global__ __launch_bounds__(256, 2)
void gemm_qkv(const __half* __restrict__ Wh)
{
    const int z = blockIdx.z;
    if (z == 0 && blockIdx.y >= 64) return;  // Q has M=8192 (64 y-tiles)

    extern __shared__ char smem[];
    const uint32_t sb = smem_u32(smem);

    const int tid  = threadIdx.x;
    const int lane = tid & 31;
    const int wid  = tid >> 5;
    const int wm   = wid >> 2;
    const int wn   = wid & 3;
    const int m0   = blockIdx.y * 128;
    const int n0   = blockIdx.x * 128;
    const int Nseq = (z == 0) ? NQ_ : NKV_;

    const __half* A  = (z == 0) ? (const __half*)g_Vh : (const __half*)g_AO;
    const __half* Ag = A + (size_t)m0 * 512;
    const __half* Wg = Wh + (size_t)z * NW_ + (size_t)n0 * 512;

    const uint32_t a_l = (uint32_t)(lane & 15) * GSTB + (uint32_t)(lane >> 4) * 16;
    const uint32_t b_l = (uint32_t)((lane & 7) + ((lane >> 4) & 1) * 8) * GSTB
                       + (uint32_t)((lane >> 3) & 1) * 16;

    float acc[4][4][4];
    #pragma unroll
    for (int i = 0; i < 4; i++)
        #pragma unroll
        for (int j = 0; j < 4; j++)
            #pragma unroll
            for (int r = 0; r < 4; r++) acc[i][j][r] = 0.f;

    // load A+W k-chunk kt into stage st (1024 x 16B segs each; 4+4/thread)
    auto load_ab = [&](int kt, int st) {
        const uint32_t SA = sb + (uint32_t)st * GSTG;
        const uint32_t SW = SA + GTILE;
        #pragma unroll
        for (int i = 0; i < 4; i++) {
            int idx = tid + i * 256;
            int r = idx >> 3, sg = idx & 7;
            cp16s(SA + (uint32_t)r * GSTB + sg * 16, Ag + (size_t)r * 512 + kt * 64 + sg * 8);
            cp16s(SW + (uint32_t)r * GSTB + sg * 16, Wg + (size_t)r * 512 + kt * 64 + sg * 8);
        }
    };

    load_ab(0, 0); CP_COMMIT();
    load_ab(1, 1); CP_COMMIT();

    for (int kt = 0; kt < 8; kt++) {
        const int st = kt % 3;
        asm volatile("cp.async.wait_group 1;");
        __syncthreads();
        // prefetch kt+2 into (kt+2)%3 == (kt-1)%3; safe: all warps passed
        // the barrier, so iter kt-1 reads of that stage are complete.
        if (kt + 2 < 8) load_ab(kt + 2, (kt + 2) % 3);
        CP_COMMIT();

        const uint32_t Ab = sb + (uint32_t)st * GSTG + (uint32_t)(wm * 64) * GSTB + a_l;
        const uint32_t Wb = sb + (uint32_t)st * GSTG + GTILE + (uint32_t)(wn * 32) * GSTB + b_l;
        #pragma unroll
        for (int ks = 0; ks < 4; ks++) {
            uint32_t bm[2][4];
            ldsm4(bm[0], Wb + ks * 32);
            ldsm4(bm[1], Wb + (uint32_t)16 * GSTB + ks * 32);
            #pragma unroll
            for (int ma = 0; ma < 4; ma++) {
                uint32_t a[4];
                ldsm4(a, Ab + (uint32_t)(ma * 16) * GSTB + ks * 32);
                #pragma unroll
                for (int nb = 0; nb < 2; nb++) {
                    mma_f16(acc[ma][nb * 2],     a, bm[nb][0], bm[nb][1]);
                    mma_f16(acc[ma][nb * 2 + 1], a, bm[nb][2], bm[nb][3]);
                }
            }
        }
    }

    // epilogue: head-split fp16
    __half* dsth = (z == 0) ? g_Qh : (z == 1) ? g_Kh : g_Vh;
    #pragma unroll
    for (int ma = 0; ma < 4; ma++) {
        #pragma unroll
        for (int na = 0; na < 4; na++) {
            const int m = m0 + wm * 64 + ma * 16 + (lane >> 2);
            const int n = n0 + wn * 32 + na * 8 + 2 * (lane & 3);
            const float* a = acc[ma][na];
            const int bb = m / Nseq;
            const int nn = m - bb * Nseq;
            const int h  = n >> 6;
            const int hd = n & 63;
            __half* base = dsth + (((size_t)bb * H_ + h) * Nseq + nn) * HD_ + hd;
            *(__half2*)base              = __floats2half2_rn(a[0], a[1]);
            *(__half2*)(base + 8 * HD_)  = __floats2half2_rn(a[2], a[3]);
        }
    }
}

// =======================================================================
// Wo GEMM (R8/R12-proven, unchanged): A = g_AO fp32 reg-staged, W fp32
// reg-staged, fp32 output. BK=32, double buffer.
// =======================================================================
#define WSTB 80
#define WO_SMEM (4 * 128 * WSTB)               // 40960 B

__global__ __launch_bounds__(256, 2)
void gemm_wo(const float* __restrict__ W, float* __restrict__ out)
{
    extern __shared__ char smem[];
    const uint32_t sb = smem_u32(smem);
    const uint32_t AO2[2] = { 0u, 10240u };
    const uint32_t WO2[2] = { 20480u, 30720u };

    const int tid  = threadIdx.x;
    const int lane = tid & 31;
    const int wid  = tid >> 5;
    const int wm   = wid >> 2;
    const int wn   = wid & 3;
    const int m0   = blockIdx.y * 128;
    const int n0   = blockIdx.x * 128;

    const uint32_t a_l = (uint32_t)(lane & 15) * WSTB + (uint32_t)(lane >> 4) * 16;
    const uint32_t b_l = (uint32_t)((lane & 7) + ((lane >> 4) & 1) * 8) * WSTB
                       + (uint32_t)((lane >> 3) & 1) * 16;

    float acc[4][4][4];
    #pragma unroll
    for (int i = 0; i < 4; i++)
        #pragma unroll
        for (int j = 0; j < 4; j++)
            #pragma unroll
            for (int r = 0; r < 4; r++) acc[i][j][r] = 0.f;

    const float* Ae = g_AO;
    const float* Wg = W + (size_t)n0 * 512;

    float4 ar[2][2]; float4 wr[2][2];

    auto ldg = [&](int kt) {
        #pragma unroll
        for (int i = 0; i < 2; i++) {
            int idx = tid + i * 256;
            int row = idx >> 2, kg = (idx & 3) * 8;
            const float* p = Ae + (size_t)(m0 + row) * 512 + kt * 32 + kg;
            ar[i][0] = *(const float4*)p;
            ar[i][1] = *(const float4*)(p + 4);
            const float* q = Wg + (size_t)row * 512 + kt * 32 + kg;
            wr[i][0] = *(const float4*)q;
            wr[i][1] = *(const float4*)(q + 4);
        }
    };
    auto sts = [&](int buf) {
        #pragma unroll
        for (int i = 0; i < 2; i++) {
            int idx = tid + i * 256;
            int row = idx >> 2, kg = (idx & 3) * 8;
            __half2 ha[4] = {
                __floats2half2_rn(ar[i][0].x, ar[i][0].y),
                __floats2half2_rn(ar[i][0].z, ar[i][0].w),
                __floats2half2_rn(ar[i][1].x, ar[i][1].y),
                __floats2half2_rn(ar[i][1].z, ar[i][1].w) };
            *(uint4*)(smem + AO2[buf] + (size_t)row * WSTB + kg * 2) = *(uint4*)ha;
            __half2 hw[4] = {
                __floats2half2_rn(wr[i][0].x, wr[i][0].y),
                __floats2half2_rn(wr[i][0].z, wr[i][0].w),
                __floats2half2_rn(wr[i][1].x, wr[i][1].y),
                __floats2half2_rn(wr[i][1].z, wr[i][1].w) };
            *(uint4*)(smem + WO2[buf] + (size_t)row * WSTB + kg * 2) = *(uint4*)hw;
        }
    };

    ldg(0);
    sts(0);
    __syncthreads();

    for (int kt = 0; kt < 16; kt++) {
        const int buf = kt & 1;
        if (kt < 15) ldg(kt + 1);

        const uint32_t Ab = sb + AO2[buf] + (uint32_t)(wm * 64) * WSTB + a_l;
        const uint32_t Wb = sb + WO2[buf] + (uint32_t)(wn * 32) * WSTB + b_l;
        #pragma unroll
        for (int ks = 0; ks < 2; ks++) {
            uint32_t bm[2][4];
            #pragma unroll
            for (int nb = 0; nb < 2; nb++)
                ldsm4(bm[nb], Wb + (uint32_t)(nb * 16) * WSTB + ks * 32);
            #pragma unroll
            for (int ma = 0; ma < 4; ma++) {
                uint32_t a[4];
                ldsm4(a, Ab + (uint32_t)(ma * 16) * WSTB + ks * 32);
                #pragma unroll
                for (int nb = 0; nb < 2; nb++) {
                    mma_f16(acc[ma][nb * 2],     a, bm[nb][0], bm[nb][1]);
                    mma_f16(acc[ma][nb * 2 + 1], a, bm[nb][2], bm[nb][3]);
                }
            }
        }
        if (kt < 15) {
            sts(buf ^ 1);
            __syncthreads();
        }
    }

    #pragma unroll
    for (int ma = 0; ma < 4; ma++) {
        #pragma unroll
        for (int na = 0; na < 4; na++) {
            const int m = m0 + wm * 64 + ma * 16 + (lane >> 2);
            const int n = n0 + wn * 32 + na * 8 + 2 * (lane & 3);
            const float* a = acc[ma][na];
            *(float2*)(out + (size_t)m * 512 + n)       = make_float2(a[0], a[1]);
            *(float2*)(out + (size_t)(m + 8) * 512 + n) = make_float2(a[2], a[3]);
        }
    }
}

// =======================================================================
// fp16 flash attention — R8/R12 kernel unchanged (203 us).
// =======================================================================
#define ASTB 144
#define KVST (2 * 64 * ASTB)
#define ATT_SMEM (128 * ASTB + 4 * KVST)      // 92160 B

__global__ __launch_bounds__(256, 2)
void attn_f16(const float* __restrict__ pos_bias)
{
    extern __shared__ char smem[];
    const uint32_t sb  = smem_u32(smem);
    const uint32_t SQ  = sb;
    const uint32_t SKV = sb + 128 * ASTB;

    const int tid  = threadIdx.x;
    const int lane = tid & 31;
    const int wid  = tid >> 5;
    const int bx = blockIdx.x;
    const int qt = bx & 7;
    const int h  = (bx >> 3) & 7;
    const int b  = bx >> 6;
    const int mrow = wid * 16;

    const uint32_t q_l = (uint32_t)(mrow + (lane & 15)) * ASTB + (uint32_t)(lane >> 4) * 16;
    const uint32_t k_l = (uint32_t)((lane & 7) + ((lane >> 4) & 1) * 8) * ASTB
                       + (uint32_t)((lane >> 3) & 1) * 16;
    const uint32_t v_l = (uint32_t)((lane & 7) + ((lane >> 3) & 1) * 8) * ASTB
                       + (uint32_t)((lane >> 4) & 1) * 16;

    const __half* Qg  = g_Qh + (((size_t)b * H_ + h) * NQ_ + (size_t)qt * 128) * HD_;
    const __half* Kg0 = g_Kh + (((size_t)b * H_ + h) * NKV_) * HD_;
    const __half* Vg0 = g_Vh + (((size_t)b * H_ + h) * NKV_) * HD_;

    auto load_kv = [&](int tt, int st) {
        const uint32_t SK = SKV + (uint32_t)st * KVST;
        const uint32_t SV = SK + 9216;
        const __half* Kg = Kg0 + (size_t)tt * 64 * HD_;
        const __half* Vg = Vg0 + (size_t)tt * 64 * HD_;
        #pragma unroll
        for (int i = 0; i < 2; i++) {
            int idx = tid + i * 256, r = idx >> 3, s = idx & 7;
            cp16s(SK + (uint32_t)r * ASTB + s * 16, Kg + (size_t)r * HD_ + s * 8);
            cp16s(SV + (uint32_t)r * ASTB + s * 16, Vg + (size_t)r * HD_ + s * 8);
        }
    };

    #pragma unroll
    for (int i = 0; i < 4; i++) {
        int idx = tid + i * 256, r = idx >> 3, s = idx & 7;
        cp16s(SQ + (uint32_t)r * ASTB + s * 16, Qg + (size_t)r * HD_ + s * 8);
    }
    load_kv(0, 0); CP_COMMIT();
    load_kv(1, 1); CP_COMMIT();
    load_kv(2, 2); CP_COMMIT();

    float o[8][4];
    #pragma unroll
    for (int na = 0; na < 8; na++)
        #pragma unroll
        for (int r = 0; r < 4; r++) o[na][r] = 0.f;
    float m_0 = -1e30f, m_1 = -1e30f, l0 = 0.f, l1 = 0.f;

    const float* bias_r0 = pos_bias
        + ((size_t)h * NQ_ + (size_t)qt * 128 + mrow + (lane >> 2)) * NKV_ + 2 * (lane & 3);

    float2 blo[8], bhi[8];
    #pragma unroll
    for (int na = 0; na < 8; na++) {
        blo[na] = *(const float2*)(bias_r0 + na * 8);
        bhi[na] = *(const float2*)(bias_r0 + (size_t)8 * NKV_ + na * 8);
    }

    for (int t = 0; t < 32; t++) {
        const uint32_t K = SKV + (uint32_t)(t & 3) * KVST;
        const uint32_t V = K + 9216;

        asm volatile("cp.async.wait_group 2;");
        __syncthreads();

        if (t + 3 < 32) load_kv(t + 3, (t + 3) & 3);
        CP_COMMIT();

        float s[8][4];
        #pragma unroll
        for (int na = 0; na < 8; na++)
            #pragma unroll
            for (int r = 0; r < 4; r++) s[na][r] = 0.f;

        #pragma unroll
        for (int ks = 0; ks < 4; ks++) {
            uint32_t a[4];
            ldsm4(a, SQ + q_l + ks * 32);
            #pragma unroll
            for (int nb = 0; nb < 4; nb++) {
                uint32_t bm[4];
                ldsm4(bm, K + k_l + (uint32_t)(nb * 16) * ASTB + ks * 32);
                mma_f16(s[nb * 2],     a, bm[0], bm[1]);
                mma_f16(s[nb * 2 + 1], a, bm[2], bm[3]);
            }
        }

        #pragma unroll
        for (int na = 0; na < 8; na++) {
            s[na][0] += blo[na].x; s[na][1] += blo[na].y;
            s[na][2] += bhi[na].x; s[na][3] += bhi[na].y;
        }

        float rmax0 = -1e30f, rmax1 = -1e30f;
        #pragma unroll
        for (int na = 0; na < 8; na++) {
            rmax0 = fmaxf(rmax0, fmaxf(s[na][0], s[na][1]));
            rmax1 = fmaxf(rmax1, fmaxf(s[na][2], s[na][3]));
        }
        rmax0 = fmaxf(rmax0, __shfl_xor_sync(0xffffffffu, rmax0, 1));
        rmax0 = fmaxf(rmax0, __shfl_xor_sync(0xffffffffu, rmax0, 2));
        rmax1 = fmaxf(rmax1, __shfl_xor_sync(0xffffffffu, rmax1, 1));
        rmax1 = fmaxf(rmax1, __shfl_xor_sync(0xffffffffu, rmax1, 2));

        const float mn0 = fmaxf(m_0, rmax0);
        const float mn1 = fmaxf(m_1, rmax1);
        const float al0 = __expf(m_0 - mn0);
        const float al1 = __expf(m_1 - mn1);
        m_0 = mn0; m_1 = mn1;

        float rs0 = 0.f, rs1 = 0.f;
        #pragma unroll
        for (int na = 0; na < 8; na++) {
            s[na][0] = __expf(s[na][0] - mn0); rs0 += s[na][0];
            s[na][1] = __expf(s[na][1] - mn0); rs0 += s[na][1];
            s[na][2] = __expf(s[na][2] - mn1); rs1 += s[na][2];
            s[na][3] = __expf(s[na][3] - mn1); rs1 += s[na][3];
        }
        l0 = l0 * al0 + rs0;
        l1 = l1 * al1 + rs1;

        uint32_t pp[4][4];
        #pragma unroll
        for (int ks = 0; ks < 4; ks++) {
            pp[ks][0] = h2pack(s[2*ks][0],   s[2*ks][1]);
            pp[ks][1] = h2pack(s[2*ks][2],   s[2*ks][3]);
            pp[ks][2] = h2pack(s[2*ks+1][0], s[2*ks+1][1]);
            pp[ks][3] = h2pack(s[2*ks+1][2], s[2*ks+1][3]);
        }

        if (t < 31) {
            const float* bb = bias_r0 + (size_t)(t + 1) * 64;
            #pragma unroll
            for (int na = 0; na < 8; na++) {
                blo[na] = *(const float2*)(bb + na * 8);
                bhi[na] = *(const float2*)(bb + (size_t)8 * NKV_ + na * 8);
            }
        }

        bool need = (al0 != 1.0f) || (al1 != 1.0f);
        if (__any_sync(0xffffffffu, need)) {
            #pragma unroll
            for (int na = 0; na < 8; na++) {
                o[na][0] *= al0; o[na][1] *= al0;
                o[na][2] *= al1; o[na][3] *= al1;
            }
        }

        #pragma unroll
        for (int ks = 0; ks < 4; ks++) {
            #pragma unroll
            for (int nb = 0; nb < 4; nb++) {
                uint32_t bm[4];
                ldsm4t(bm, V + v_l + (uint32_t)(ks * 16) * ASTB + nb * 32);
                mma_f16(o[nb * 2],     pp[ks], bm[0], bm[1]);
                mma_f16(o[nb * 2 + 1], pp[ks], bm[2], bm[3]);
            }
        }
    }

    l0 += __shfl_xor_sync(0xffffffffu, l0, 1);
    l0 += __shfl_xor_sync(0xffffffffu, l0, 2);
    l1 += __shfl_xor_sync(0xffffffffu, l1, 1);
    l1 += __shfl_xor_sync(0xffffffffu, l1, 2);
    const float inv0 = 1.0f / l0;
    const float inv1 = 1.0f / l1;

    const size_t r0 = (size_t)b * NQ_ + (size_t)qt * 128 + mrow + (lane >> 2);
    #pragma unroll
    for (int na = 0; na < 8; na++) {
        const int col = h * HD_ + na * 8 + 2 * (lane & 3);
        *(float2*)(g_AO + r0 * D_ + col) =
            make_float2(o[na][0] * inv0, o[na][1] * inv0);
        *(float2*)(g_AO + (r0 + 8) * D_ + col) =
            make_float2(o[na][2] * inv1, o[na][3] * inv1);
    }
}

// =======================================================================
// launch — stream-ordered aliasing:
//   x_fp16 in g_Vh (Q proj reads before V proj overwrites)
//   enc_fp16 in g_AO (K/V proj read before attention overwrites)
//   Wq/Wk/Wv fp16 in d_out (projections read before gemm_wo overwrites)
// =======================================================================
extern "C" void kernel_launch(void* const* d_in, const int* in_sizes, int n_in,
                              void* d_out, int out_size)
{
    const float* x        = (const float*)d_in[0];
    const float* enc      = (const float*)d_in[1];
    const float* pos_bias = (const float*)d_in[2];
    const float* Wq       = (const float*)d_in[3];
    const float* Wk       = (const float*)d_in[4];
    const float* Wv       = (const float*)d_in[5];
    const float* Wo       = (const float*)d_in[6];
    float* out = (float*)d_out;
    __half* wh = (__half*)d_out;   // weight-fp16 scratch (overwritten at the end)

    cudaFuncSetAttribute(gemm_qkv, cudaFuncAttributeMaxDynamicSharedMemorySize, GEMM_SMEM);
    cudaFuncSetAttribute(gemm_wo,  cudaFuncAttributeMaxDynamicSharedMemorySize, WO_SMEM);
    cudaFuncSetAttribute(attn_f16, cudaFuncAttributeMaxDynamicSharedMemorySize, ATT_SMEM);

    // staging: x, enc, Wq/Wk/Wv -> fp16
    cvt_all<<<(CVT_TOTAL / 8 + 255) / 256, 256>>>(x, enc, Wq, Wk, Wv, wh);
    // fused QKV projections (pure fp16, z = 0/1/2)
    gemm_qkv<<<dim3(4, 128, 3), 256, GEMM_SMEM>>>(wh);
    // attention (overwrites g_AO with fp32 AO)
    attn_f16<<<B_ * H_ * (NQ_ / 128), 256, ATT_SMEM>>>(pos_bias);
    // output projection (overwrites d_out with the final result)
    gemm_wo<<<dim3(4, 64), 256, WO_SMEM>>>(Wo, out);
}

// round 14
// speedup vs baseline: 1.1589x; 1.0197x over previous
#include <cuda_runtime.h>
#include <cuda_fp16.h>
#include <cstdint>

#define B_  8
#define H_  8
#define NQ_ 1024
#define NKV_ 2048
#define D_  512
#define HD_ 64

// ---------------- scratch (56 MB, unchanged) ----------------------------
// Symbols referenced ONLY from device code (host-side decay of __device__
// symbols caused the R9/R10 resource violations).
__device__ __half g_Qh [B_ * H_ * NQ_  * HD_];   //  8 MB
__device__ __half g_Kh [B_ * H_ * NKV_ * HD_];   // 16 MB; tail reused for Wo fp16
__device__ __half g_Vh [B_ * H_ * NKV_ * HD_];   // 16 MB; first 8MB doubles as x_fp16
__device__ float  g_AO [B_ * NQ_ * D_];          // 16 MB; enc_fp16, then AO fp16

// ---------------- helpers ----------------
__device__ __forceinline__ uint32_t smem_u32(const void* p) {
    uint32_t a;
    asm("{ .reg .u64 t; cvta.to.shared.u64 t, %1; cvt.u32.u64 %0, t; }" : "=r"(a) : "l"(p));
    return a;
}
__device__ __forceinline__ void cp16s(uint32_t d, const void* src) {
    asm volatile("cp.async.cg.shared.global [%0], [%1], 16;" :: "r"(d), "l"(src));
}
#define CP_COMMIT() asm volatile("cp.async.commit_group;")

__device__ __forceinline__ void mma_f16(float* c, const uint32_t* a, uint32_t b0, uint32_t b1) {
    asm volatile(
        "mma.sync.aligned.m16n8k16.row.col.f32.f16.f16.f32 "
        "{%0,%1,%2,%3}, {%4,%5,%6,%7}, {%8,%9}, {%0,%1,%2,%3};"
        : "+f"(c[0]), "+f"(c[1]), "+f"(c[2]), "+f"(c[3])
        : "r"(a[0]), "r"(a[1]), "r"(a[2]), "r"(a[3]), "r"(b0), "r"(b1));
}
__device__ __forceinline__ void ldsm4(uint32_t* r, uint32_t addr) {
    asm volatile("ldmatrix.sync.aligned.m8n8.x4.shared.b16 {%0,%1,%2,%3}, [%4];"
                 : "=r"(r[0]), "=r"(r[1]), "=r"(r[2]), "=r"(r[3]) : "r"(addr));
}
__device__ __forceinline__ void ldsm4t(uint32_t* r, uint32_t addr) {
    asm volatile("ldmatrix.sync.aligned.m8n8.x4.trans.shared.b16 {%0,%1,%2,%3}, [%4];"
                 : "=r"(r[0]), "=r"(r[1]), "=r"(r[2]), "=r"(r[3]) : "r"(addr));
}
__device__ __forceinline__ uint32_t h2pack(float a, float b) {
    __half2 h = __floats2half2_rn(a, b);
    return *(uint32_t*)&h;
}

// =======================================================================
// Fused fp32->fp16 convert: x -> g_Vh bytes, enc -> g_AO bytes,
// Wq/Wk/Wv -> wh (= d_out scratch, legal until gemm_wo_h overwrites).
// =======================================================================
#define NX_ (B_ * NQ_ * D_)        // 4194304
#define NE_ (B_ * NKV_ * D_)       // 8388608
#define NW_ (D_ * D_)              // 262144
#define CVT_TOTAL (NX_ + NE_ + 3 * NW_)

__device__ __forceinline__ void cvt8(const float* __restrict__ s, __half* __restrict__ d, int i) {
    float4 a = *(const float4*)(s + i);
    float4 b = *(const float4*)(s + i + 4);
    __half2 h[4] = { __floats2half2_rn(a.x, a.y), __floats2half2_rn(a.z, a.w),
                     __floats2half2_rn(b.x, b.y), __floats2half2_rn(b.z, b.w) };
    *(uint4*)(d + i) = *(uint4*)h;
}

__global__ __launch_bounds__(256)
void cvt_all(const float* __restrict__ x, const float* __restrict__ enc,
             const float* __restrict__ wq, const float* __restrict__ wk,
             const float* __restrict__ wv, __half* __restrict__ wh)
{
    int i = (blockIdx.x * 256 + threadIdx.x) * 8;
    if (i < NX_) {
        cvt8(x, (__half*)g_Vh, i);
    } else if (i < NX_ + NE_) {
        cvt8(enc, (__half*)g_AO, i - NX_);
    } else if (i < NX_ + NE_ + NW_) {
        cvt8(wq, wh, i - NX_ - NE_);
    } else if (i < NX_ + NE_ + 2 * NW_) {
        cvt8(wk, wh + NW_, i - NX_ - NE_ - NW_);
    } else if (i < CVT_TOTAL) {
        cvt8(wv, wh + 2 * NW_, i - NX_ - NE_ - 2 * NW_);
    }
}

// Wo -> fp16 into g_Kh (free after attention). Launched post-attention.
__global__ __launch_bounds__(256)
void cvt_wo(const float* __restrict__ wo)
{
    int i = (blockIdx.x * 256 + threadIdx.x) * 8;
    if (i < NW_) cvt8(wo, g_Kh, i);
}

// =======================================================================
// Fused QKV projection (R13-proven): pure-fp16 GEMM, both operands via
// 3-stage cp.async. BK=64, tile 128x128. Inner loop = ldsm + mma only.
// blockIdx.z: 0 -> Q (A = x_fp16 in g_Vh, M=8192), 1 -> K, 2 -> V
// (A = enc_fp16 in g_AO, M=16384). W = wh + z*NW_ (fp16 in d_out scratch).
// =======================================================================
#define GSTB 144
#define GTILE (128 * GSTB)                   // 18432 B
#define GSTG  (2 * GTILE)                    // A+W per stage = 36864 B
#define GEMM_SMEM (3 * GSTG)                 // 110592 B

__global__ __launch_bounds__(256, 2)
void gemm_qkv(const __half* __restrict__ Wh)
{
    const int z = blockIdx.z;
    if (z == 0 && blockIdx.y >= 64) return;

    extern __shared__ char smem[];
    const uint32_t sb = smem_u32(smem);

    const int tid  = threadIdx.x;
    const int lane = tid & 31;
    const int wid  = tid >> 5;
    const int wm   = wid >> 2;
    const int wn   = wid & 3;
    const int m0   = blockIdx.y * 128;
    const int n0   = blockIdx.x * 128;
    const int Nseq = (z == 0) ? NQ_ : NKV_;

    const __half* A  = (z == 0) ? (const __half*)g_Vh : (const __half*)g_AO;
    const __half* Ag = A + (size_t)m0 * 512;
    const __half* Wg = Wh + (size_t)z * NW_ + (size_t)n0 * 512;

    const uint32_t a_l = (uint32_t)(lane & 15) * GSTB + (uint32_t)(lane >> 4) * 16;
    const uint32_t b_l = (uint32_t)((lane & 7) + ((lane >> 4) & 1) * 8) * GSTB
                       + (uint32_t)((lane >> 3) & 1) * 16;

    float acc[4][4][4];
    #pragma unroll
    for (int i = 0; i < 4; i++)
        #pragma unroll
        for (int j = 0; j < 4; j++)
            #pragma unroll
            for (int r = 0; r < 4; r++) acc[i][j][r] = 0.f;

    auto load_ab = [&](int kt, int st) {
        const uint32_t SA = sb + (uint32_t)st * GSTG;
        const uint32_t SW = SA + GTILE;
        #pragma unroll
        for (int i = 0; i < 4; i++) {
            int idx = tid + i * 256;
            int r = idx >> 3, sg = idx & 7;
            cp16s(SA + (uint32_t)r * GSTB + sg * 16, Ag + (size_t)r * 512 + kt * 64 + sg * 8);
            cp16s(SW + (uint32_t)r * GSTB + sg * 16, Wg + (size_t)r * 512 + kt * 64 + sg * 8);
        }
    };

    load_ab(0, 0); CP_COMMIT();
    load_ab(1, 1); CP_COMMIT();

    for (int kt = 0; kt < 8; kt++) {
        const int st = kt % 3;
        asm volatile("cp.async.wait_group 1;");
        __syncthreads();
        if (kt + 2 < 8) load_ab(kt + 2, (kt + 2) % 3);
        CP_COMMIT();

        const uint32_t Ab = sb + (uint32_t)st * GSTG + (uint32_t)(wm * 64) * GSTB + a_l;
        const uint32_t Wb = sb + (uint32_t)st * GSTG + GTILE + (uint32_t)(wn * 32) * GSTB + b_l;
        #pragma unroll
        for (int ks = 0; ks < 4; ks++) {
            uint32_t bm[2][4];
            ldsm4(bm[0], Wb + ks * 32);
            ldsm4(bm[1], Wb + (uint32_t)16 * GSTB + ks * 32);
            #pragma unroll
            for (int ma = 0; ma < 4; ma++) {
                uint32_t a[4];
                ldsm4(a, Ab + (uint32_t)(ma * 16) * GSTB + ks * 32);
                #pragma unroll
                for (int nb = 0; nb < 2; nb++) {
                    mma_f16(acc[ma][nb * 2],     a, bm[nb][0], bm[nb][1]);
                    mma_f16(acc[ma][nb * 2 + 1], a, bm[nb][2], bm[nb][3]);
                }
            }
        }
    }

    __half* dsth = (z == 0) ? g_Qh : (z == 1) ? g_Kh : g_Vh;
    #pragma unroll
    for (int ma = 0; ma < 4; ma++) {
        #pragma unroll
        for (int na = 0; na < 4; na++) {
            const int m = m0 + wm * 64 + ma * 16 + (lane >> 2);
            const int n = n0 + wn * 32 + na * 8 + 2 * (lane & 3);
            const float* a = acc[ma][na];
            const int bb = m / Nseq;
            const int nn = m - bb * Nseq;
            const int h  = n >> 6;
            const int hd = n & 63;
            __half* base = dsth + (((size_t)bb * H_ + h) * Nseq + nn) * HD_ + hd;
            *(__half2*)base              = __floats2half2_rn(a[0], a[1]);
            *(__half2*)(base + 8 * HD_)  = __floats2half2_rn(a[2], a[3]);
        }
    }
}

// =======================================================================
// Wo GEMM, pure fp16 (R13 pipeline): A = AO fp16 (g_AO bytes, written by
// attention), W = Wo fp16 (g_Kh, written by cvt_wo). fp32 output.
// =======================================================================
__global__ __launch_bounds__(256, 2)
void gemm_wo_h(float* __restrict__ out)
{
    extern __shared__ char smem[];
    const uint32_t sb = smem_u32(smem);

    const int tid  = threadIdx.x;
    const int lane = tid & 31;
    const int wid  = tid >> 5;
    const int wm   = wid >> 2;
    const int wn   = wid & 3;
    const int m0   = blockIdx.y * 128;
    const int n0   = blockIdx.x * 128;

    const __half* Ag = (const __half*)g_AO + (size_t)m0 * 512;
    const __half* Wg = g_Kh + (size_t)n0 * 512;

    const uint32_t a_l = (uint32_t)(lane & 15) * GSTB + (uint32_t)(lane >> 4) * 16;
    const uint32_t b_l = (uint32_t)((lane & 7) + ((lane >> 4) & 1) * 8) * GSTB
                       + (uint32_t)((lane >> 3) & 1) * 16;

    float acc[4][4][4];
    #pragma unroll
    for (int i = 0; i < 4; i++)
        #pragma unroll
        for (int j = 0; j < 4; j++)
            #pragma unroll
            for (int r = 0; r < 4; r++) acc[i][j][r] = 0.f;

    auto load_ab = [&](int kt, int st) {
        const uint32_t SA = sb + (uint32_t)st * GSTG;
        const uint32_t SW = SA + GTILE;
        #pragma unroll
        for (int i = 0; i < 4; i++) {
            int idx = tid + i * 256;
            int r = idx >> 3, sg = idx & 7;
            cp16s(SA + (uint32_t)r * GSTB + sg * 16, Ag + (size_t)r * 512 + kt * 64 + sg * 8);
            cp16s(SW + (uint32_t)r * GSTB + sg * 16, Wg + (size_t)r * 512 + kt * 64 + sg * 8);
        }
    };

    load_ab(0, 0); CP_COMMIT();
    load_ab(1, 1); CP_COMMIT();

    for (int kt = 0; kt < 8; kt++) {
        const int st = kt % 3;
        asm volatile("cp.async.wait_group 1;");
        __syncthreads();
        if (kt + 2 < 8) load_ab(kt + 2, (kt + 2) % 3);
        CP_COMMIT();

        const uint32_t Ab = sb + (uint32_t)st * GSTG + (uint32_t)(wm * 64) * GSTB + a_l;
        const uint32_t Wb = sb + (uint32_t)st * GSTG + GTILE + (uint32_t)(wn * 32) * GSTB + b_l;
        #pragma unroll
        for (int ks = 0; ks < 4; ks++) {
            uint32_t bm[2][4];
            ldsm4(bm[0], Wb + ks * 32);
            ldsm4(bm[1], Wb + (uint32_t)16 * GSTB + ks * 32);
            #pragma unroll
            for (int ma = 0; ma < 4; ma++) {
                uint32_t a[4];
                ldsm4(a, Ab + (uint32_t)(ma * 16) * GSTB + ks * 32);
                #pragma unroll
                for (int nb = 0; nb < 2; nb++) {
                    mma_f16(acc[ma][nb * 2],     a, bm[nb][0], bm[nb][1]);
                    mma_f16(acc[ma][nb * 2 + 1], a, bm[nb][2], bm[nb][3]);
                }
            }
        }
    }

    #pragma unroll
    for (int ma = 0; ma < 4; ma++) {
        #pragma unroll
        for (int na = 0; na < 4; na++) {
            const int m = m0 + wm * 64 + ma * 16 + (lane >> 2);
            const int n = n0 + wn * 32 + na * 8 + 2 * (lane & 3);
            const float* a = acc[ma][na];
            *(float2*)(out + (size_t)m * 512 + n)       = make_float2(a[0], a[1]);
            *(float2*)(out + (size_t)(m + 8) * 512 + n) = make_float2(a[2], a[3]);
        }
    }
}

// =======================================================================
// fp16 flash attention — R8/R13 loop unchanged; epilogue now writes
// fp16 AO into g_AO bytes (identical rounding: gemm_wo staged to fp16).
// =======================================================================
#define ASTB 144
#define KVST (2 * 64 * ASTB)
#define ATT_SMEM (128 * ASTB + 4 * KVST)      // 92160 B

__global__ __launch_bounds__(256, 2)
void attn_f16(const float* __restrict__ pos_bias)
{
    extern __shared__ char smem[];
    const uint32_t sb  = smem_u32(smem);
    const uint32_t SQ  = sb;
    const uint32_t SKV = sb + 128 * ASTB;

    const int tid  = threadIdx.x;
    const int lane = tid & 31;
    const int wid  = tid >> 5;
    const int bx = blockIdx.x;
    const int qt = bx & 7;
    const int h  = (bx >> 3) & 7;
    const int b  = bx >> 6;
    const int mrow = wid * 16;

    const uint32_t q_l = (uint32_t)(mrow + (lane & 15)) * ASTB + (uint32_t)(lane >> 4) * 16;
    const uint32_t k_l = (uint32_t)((lane & 7) + ((lane >> 4) & 1) * 8) * ASTB
                       + (uint32_t)((lane >> 3) & 1) * 16;
    const uint32_t v_l = (uint32_t)((lane & 7) + ((lane >> 3) & 1) * 8) * ASTB
                       + (uint32_t)((lane >> 4) & 1) * 16;

    const __half* Qg  = g_Qh + (((size_t)b * H_ + h) * NQ_ + (size_t)qt * 128) * HD_;
    const __half* Kg0 = g_Kh + (((size_t)b * H_ + h) * NKV_) * HD_;
    const __half* Vg0 = g_Vh + (((size_t)b * H_ + h) * NKV_) * HD_;

    auto load_kv = [&](int tt, int st) {
        const uint32_t SK = SKV + (uint32_t)st * KVST;
        const uint32_t SV = SK + 9216;
        const __half* Kg = Kg0 + (size_t)tt * 64 * HD_;
        const __half* Vg = Vg0 + (size_t)tt * 64 * HD_;
        #pragma unroll
        for (int i = 0; i < 2; i++) {
            int idx = tid + i * 256, r = idx >> 3, s = idx & 7;
            cp16s(SK + (uint32_t)r * ASTB + s * 16, Kg + (size_t)r * HD_ + s * 8);
            cp16s(SV + (uint32_t)r * ASTB + s * 16, Vg + (size_t)r * HD_ + s * 8);
        }
    };

    #pragma unroll
    for (int i = 0; i < 4; i++) {
        int idx = tid + i * 256, r = idx >> 3, s = idx & 7;
        cp16s(SQ + (uint32_t)r * ASTB + s * 16, Qg + (size_t)r * HD_ + s * 8);
    }
    load_kv(0, 0); CP_COMMIT();
    load_kv(1, 1); CP_COMMIT();
    load_kv(2, 2); CP_COMMIT();

    float o[8][4];
    #pragma unroll
    for (int na = 0; na < 8; na++)
        #pragma unroll
        for (int r = 0; r < 4; r++) o[na][r] = 0.f;
    float m_0 = -1e30f, m_1 = -1e30f, l0 = 0.f, l1 = 0.f;

    const float* bias_r0 = pos_bias
        + ((size_t)h * NQ_ + (size_t)qt * 128 + mrow + (lane >> 2)) * NKV_ + 2 * (lane & 3);

    float2 blo[8], bhi[8];
    #pragma unroll
    for (int na = 0; na < 8; na++) {
        blo[na] = *(const float2*)(bias_r0 + na * 8);
        bhi[na] = *(const float2*)(bias_r0 + (size_t)8 * NKV_ + na * 8);
    }

    for (int t = 0; t < 32; t++) {
        const uint32_t K = SKV + (uint32_t)(t & 3) * KVST;
        const uint32_t V = K + 9216;

        asm volatile("cp.async.wait_group 2;");
        __syncthreads();

        if (t + 3 < 32) load_kv(t + 3, (t + 3) & 3);
        CP_COMMIT();

        float s[8][4];
        #pragma unroll
        for (int na = 0; na < 8; na++)
            #pragma unroll
            for (int r = 0; r < 4; r++) s[na][r] = 0.f;

        #pragma unroll
        for (int ks = 0; ks < 4; ks++) {
            uint32_t a[4];
            ldsm4(a, SQ + q_l + ks * 32);
            #pragma unroll
            for (int nb = 0; nb < 4; nb++) {
                uint32_t bm[4];
                ldsm4(bm, K + k_l + (uint32_t)(nb * 16) * ASTB + ks * 32);
                mma_f16(s[nb * 2],     a, bm[0], bm[1]);
                mma_f16(s[nb * 2 + 1], a, bm[2], bm[3]);
            }
        }

        #pragma unroll
        for (int na = 0; na < 8; na++) {
            s[na][0] += blo[na].x; s[na][1] += blo[na].y;
            s[na][2] += bhi[na].x; s[na][3] += bhi[na].y;
        }

        float rmax0 = -1e30f, rmax1 = -1e30f;
        #pragma unroll
        for (int na = 0; na < 8; na++) {
            rmax0 = fmaxf(rmax0, fmaxf(s[na][0], s[na][1]));
            rmax1 = fmaxf(rmax1, fmaxf(s[na][2], s[na][3]));
        }
        rmax0 = fmaxf(rmax0, __shfl_xor_sync(0xffffffffu, rmax0, 1));
        rmax0 = fmaxf(rmax0, __shfl_xor_sync(0xffffffffu, rmax0, 2));
        rmax1 = fmaxf(rmax1, __shfl_xor_sync(0xffffffffu, rmax1, 1));
        rmax1 = fmaxf(rmax1, __shfl_xor_sync(0xffffffffu, rmax1, 2));

        const float mn0 = fmaxf(m_0, rmax0);
        const float mn1 = fmaxf(m_1, rmax1);
        const float al0 = __expf(m_0 - mn0);
        const float al1 = __expf(m_1 - mn1);
        m_0 = mn0; m_1 = mn1;

        float rs0 = 0.f, rs1 = 0.f;
        #pragma unroll
        for (int na = 0; na < 8; na++) {
            s[na][0] = __expf(s[na][0] - mn0); rs0 += s[na][0];
            s[na][1] = __expf(s[na][1] - mn0); rs0 += s[na][1];
            s[na][2] = __expf(s[na][2] - mn1); rs1 += s[na][2];
            s[na][3] = __expf(s[na][3] - mn1); rs1 += s[na][3];
        }
        l0 = l0 * al0 + rs0;
        l1 = l1 * al1 + rs1;

        uint32_t pp[4][4];
        #pragma unroll
        for (int ks = 0; ks < 4; ks++) {
            pp[ks][0] = h2pack(s[2*ks][0],   s[2*ks][1]);
            pp[ks][1] = h2pack(s[2*ks][2],   s[2*ks][3]);
            pp[ks][2] = h2pack(s[2*ks+1][0], s[2*ks+1][1]);
            pp[ks][3] = h2pack(s[2*ks+1][2], s[2*ks+1][3]);
        }

        if (t < 31) {
            const float* bb = bias_r0 + (size_t)(t + 1) * 64;
            #pragma unroll
            for (int na = 0; na < 8; na++) {
                blo[na] = *(const float2*)(bb + na * 8);
                bhi[na] = *(const float2*)(bb + (size_t)8 * NKV_ + na * 8);
            }
        }

        bool need = (al0 != 1.0f) || (al1 != 1.0f);
        if (__any_sync(0xffffffffu, need)) {
            #pragma unroll
            for (int na = 0; na < 8; na++) {
                o[na][0] *= al0; o[na][1] *= al0;
                o[na][2] *= al1; o[na][3] *= al1;
            }
        }

        #pragma unroll
        for (int ks = 0; ks < 4; ks++) {
            #pragma unroll
            for (int nb = 0; nb < 4; nb++) {
                uint32_t bm[4];
                ldsm4t(bm, V + v_l + (uint32_t)(ks * 16) * ASTB + nb * 32);
                mma_f16(o[nb * 2],     pp[ks], bm[0], bm[1]);
                mma_f16(o[nb * 2 + 1], pp[ks], bm[2], bm[3]);
            }
        }
    }

    l0 += __shfl_xor_sync(0xffffffffu, l0, 1);
    l0 += __shfl_xor_sync(0xffffffffu, l0, 2);
    l1 += __shfl_xor_sync(0xffffffffu, l1, 1);
    l1 += __shfl_xor_sync(0xffffffffu, l1, 2);
    const float inv0 = 1.0f / l0;
    const float inv1 = 1.0f / l1;

    // epilogue: fp16 AO into g_AO bytes (same rounding as old staging path)
    __half* aoh = (__half*)g_AO;
    const size_t r0 = (size_t)b * NQ_ + (size_t)qt * 128 + mrow + (lane >> 2);
    #pragma unroll
    for (int na = 0; na < 8; na++) {
        const int col = h * HD_ + na * 8 + 2 * (lane & 3);
        *(__half2*)(aoh + r0 * D_ + col) =
            __floats2half2_rn(o[na][0] * inv0, o[na][1] * inv0);
        *(__half2*)(aoh + (r0 + 8) * D_ + col) =
            __floats2half2_rn(o[na][2] * inv1, o[na][3] * inv1);
    }
}

// =======================================================================
// launch — stream-ordered aliasing:
//   x_fp16 in g_Vh        (Q proj reads before V proj overwrites)
//   enc_fp16 in g_AO      (K/V proj read before attention overwrites)
//   Wq/Wk/Wv fp16 in d_out(projections read before gemm_wo_h overwrites)
//   AO fp16 in g_AO       (attention writes, gemm_wo_h reads)
//   Wo fp16 in g_Kh       (cvt_wo writes after attention frees g_Kh)
// =======================================================================
extern "C" void kernel_launch(void* const* d_in, const int* in_sizes, int n_in,
                              void* d_out, int out_size)
{
    const float* x        = (const float*)d_in[0];
    const float* enc      = (const float*)d_in[1];
    const float* pos_bias = (const float*)d_in[2];
    const float* Wq       = (const float*)d_in[3];
    const float* Wk       = (const float*)d_in[4];
    const float* Wv       = (const float*)d_in[5];
    const float* Wo       = (const float*)d_in[6];
    float* out = (float*)d_out;
    __half* wh = (__half*)d_out;   // weight scratch until gemm_wo_h writes

    cudaFuncSetAttribute(gemm_qkv,  cudaFuncAttributeMaxDynamicSharedMemorySize, GEMM_SMEM);
    cudaFuncSetAttribute(gemm_wo_h, cudaFuncAttributeMaxDynamicSharedMemorySize, GEMM_SMEM);
    cudaFuncSetAttribute(attn_f16,  cudaFuncAttributeMaxDynamicSharedMemorySize, ATT_SMEM);

    cvt_all<<<(CVT_TOTAL / 8 + 255) / 256, 256>>>(x, enc, Wq, Wk, Wv, wh);
    gemm_qkv<<<dim3(4, 128, 3), 256, GEMM_SMEM>>>(wh);
    attn_f16<<<B_ * H_ * (NQ_ / 128), 256, ATT_SMEM>>>(pos_bias);
    cvt_wo<<<(NW_ / 8 + 255) / 256, 256>>>(Wo);
    gemm_wo_h<<<dim3(4, 64), 256, GEMM_SMEM>>>(out);
}

// round 15
// speedup vs baseline: 1.1648x; 1.0051x over previous
#include <cuda_runtime.h>
#include <cuda_fp16.h>
#include <cstdint>

#define B_  8
#define H_  8
#define NQ_ 1024
#define NKV_ 2048
#define D_  512
#define HD_ 64

// ---------------- scratch (56 MB, unchanged) ----------------------------
// Symbols referenced ONLY from device code (host-side decay of __device__
// symbols caused the R9/R10 resource violations).
__device__ __half g_Qh [B_ * H_ * NQ_  * HD_];   //  8 MB
__device__ __half g_Kh [B_ * H_ * NKV_ * HD_];   // 16 MB; reused for Wo fp16
__device__ __half g_Vh [B_ * H_ * NKV_ * HD_];   // 16 MB; first 8MB doubles as x_fp16
__device__ float  g_AO [B_ * NQ_ * D_];          // 16 MB; enc_fp16, then AO fp16

// ---------------- helpers ----------------
__device__ __forceinline__ uint32_t smem_u32(const void* p) {
    uint32_t a;
    asm("{ .reg .u64 t; cvta.to.shared.u64 t, %1; cvt.u32.u64 %0, t; }" : "=r"(a) : "l"(p));
    return a;
}
__device__ __forceinline__ void cp16s(uint32_t d, const void* src) {
    asm volatile("cp.async.cg.shared.global [%0], [%1], 16;" :: "r"(d), "l"(src));
}
#define CP_COMMIT() asm volatile("cp.async.commit_group;")

__device__ __forceinline__ void mma_f16(float* c, const uint32_t* a, uint32_t b0, uint32_t b1) {
    asm volatile(
        "mma.sync.aligned.m16n8k16.row.col.f32.f16.f16.f32 "
        "{%0,%1,%2,%3}, {%4,%5,%6,%7}, {%8,%9}, {%0,%1,%2,%3};"
        : "+f"(c[0]), "+f"(c[1]), "+f"(c[2]), "+f"(c[3])
        : "r"(a[0]), "r"(a[1]), "r"(a[2]), "r"(a[3]), "r"(b0), "r"(b1));
}
__device__ __forceinline__ void ldsm4(uint32_t* r, uint32_t addr) {
    asm volatile("ldmatrix.sync.aligned.m8n8.x4.shared.b16 {%0,%1,%2,%3}, [%4];"
                 : "=r"(r[0]), "=r"(r[1]), "=r"(r[2]), "=r"(r[3]) : "r"(addr));
}
__device__ __forceinline__ void ldsm4t(uint32_t* r, uint32_t addr) {
    asm volatile("ldmatrix.sync.aligned.m8n8.x4.trans.shared.b16 {%0,%1,%2,%3}, [%4];"
                 : "=r"(r[0]), "=r"(r[1]), "=r"(r[2]), "=r"(r[3]) : "r"(addr));
}
__device__ __forceinline__ uint32_t h2pack(float a, float b) {
    __half2 h = __floats2half2_rn(a, b);
    return *(uint32_t*)&h;
}

// =======================================================================
// Fused fp32->fp16 convert: x -> g_Vh bytes, enc -> g_AO bytes,
// Wq/Wk/Wv -> wh (= d_out scratch, legal until gemm_wo_h overwrites).
// =======================================================================
#define NX_ (B_ * NQ_ * D_)        // 4194304
#define NE_ (B_ * NKV_ * D_)       // 8388608
#define NW_ (D_ * D_)              // 262144
#define CVT_TOTAL (NX_ + NE_ + 3 * NW_)

__device__ __forceinline__ void cvt8(const float* __restrict__ s, __half* __restrict__ d, int i) {
    float4 a = *(const float4*)(s + i);
    float4 b = *(const float4*)(s + i + 4);
    __half2 h[4] = { __floats2half2_rn(a.x, a.y), __floats2half2_rn(a.z, a.w),
                     __floats2half2_rn(b.x, b.y), __floats2half2_rn(b.z, b.w) };
    *(uint4*)(d + i) = *(uint4*)h;
}

__global__ __launch_bounds__(256)
void cvt_all(const float* __restrict__ x, const float* __restrict__ enc,
             const float* __restrict__ wq, const float* __restrict__ wk,
             const float* __restrict__ wv, __half* __restrict__ wh)
{
    int i = (blockIdx.x * 256 + threadIdx.x) * 8;
    if (i < NX_) {
        cvt8(x, (__half*)g_Vh, i);
    } else if (i < NX_ + NE_) {
        cvt8(enc, (__half*)g_AO, i - NX_);
    } else if (i < NX_ + NE_ + NW_) {
        cvt8(wq, wh, i - NX_ - NE_);
    } else if (i < NX_ + NE_ + 2 * NW_) {
        cvt8(wk, wh + NW_, i - NX_ - NE_ - NW_);
    } else if (i < CVT_TOTAL) {
        cvt8(wv, wh + 2 * NW_, i - NX_ - NE_ - 2 * NW_);
    }
}

// Wo -> fp16 into g_Kh (free after attention). Launched post-attention.
__global__ __launch_bounds__(256)
void cvt_wo(const float* __restrict__ wo)
{
    int i = (blockIdx.x * 256 + threadIdx.x) * 8;
    if (i < NW_) cvt8(wo, g_Kh, i);
}

// =======================================================================
// Fused QKV projection (R13-proven): pure-fp16 GEMM, both operands via
// 3-stage cp.async. BK=64, tile 128x128. Inner loop = ldsm + mma only.
// blockIdx.z: 0 -> Q (A = x_fp16 in g_Vh, M=8192), 1 -> K, 2 -> V
// (A = enc_fp16 in g_AO, M=16384). W = wh + z*NW_ (fp16 in d_out scratch).
// =======================================================================
#define GSTB 144
#define GTILE (128 * GSTB)                   // 18432 B
#define GSTG  (2 * GTILE)                    // A+W per stage = 36864 B
#define GEMM_SMEM (3 * GSTG)                 // 110592 B

__global__ __launch_bounds__(256, 2)
void gemm_qkv(const __half* __restrict__ Wh)
{
    const int z = blockIdx.z;
    if (z == 0 && blockIdx.y >= 64) return;

    extern __shared__ char smem[];
    const uint32_t sb = smem_u32(smem);

    const int tid  = threadIdx.x;
    const int lane = tid & 31;
    const int wid  = tid >> 5;
    const int wm   = wid >> 2;
    const int wn   = wid & 3;
    const int m0   = blockIdx.y * 128;
    const int n0   = blockIdx.x * 128;
    const int Nseq = (z == 0) ? NQ_ : NKV_;

    const __half* A  = (z == 0) ? (const __half*)g_Vh : (const __half*)g_AO;
    const __half* Ag = A + (size_t)m0 * 512;
    const __half* Wg = Wh + (size_t)z * NW_ + (size_t)n0 * 512;

    const uint32_t a_l = (uint32_t)(lane & 15) * GSTB + (uint32_t)(lane >> 4) * 16;
    const uint32_t b_l = (uint32_t)((lane & 7) + ((lane >> 4) & 1) * 8) * GSTB
                       + (uint32_t)((lane >> 3) & 1) * 16;

    float acc[4][4][4];
    #pragma unroll
    for (int i = 0; i < 4; i++)
        #pragma unroll
        for (int j = 0; j < 4; j++)
            #pragma unroll
            for (int r = 0; r < 4; r++) acc[i][j][r] = 0.f;

    auto load_ab = [&](int kt, int st) {
        const uint32_t SA = sb + (uint32_t)st * GSTG;
        const uint32_t SW = SA + GTILE;
        #pragma unroll
        for (int i = 0; i < 4; i++) {
            int idx = tid + i * 256;
            int r = idx >> 3, sg = idx & 7;
            cp16s(SA + (uint32_t)r * GSTB + sg * 16, Ag + (size_t)r * 512 + kt * 64 + sg * 8);
            cp16s(SW + (uint32_t)r * GSTB + sg * 16, Wg + (size_t)r * 512 + kt * 64 + sg * 8);
        }
    };

    load_ab(0, 0); CP_COMMIT();
    load_ab(1, 1); CP_COMMIT();

    for (int kt = 0; kt < 8; kt++) {
        const int st = kt % 3;
        asm volatile("cp.async.wait_group 1;");
        __syncthreads();
        if (kt + 2 < 8) load_ab(kt + 2, (kt + 2) % 3);
        CP_COMMIT();

        const uint32_t Ab = sb + (uint32_t)st * GSTG + (uint32_t)(wm * 64) * GSTB + a_l;
        const uint32_t Wb = sb + (uint32_t)st * GSTG + GTILE + (uint32_t)(wn * 32) * GSTB + b_l;
        #pragma unroll
        for (int ks = 0; ks < 4; ks++) {
            uint32_t bm[2][4];
            ldsm4(bm[0], Wb + ks * 32);
            ldsm4(bm[1], Wb + (uint32_t)16 * GSTB + ks * 32);
            #pragma unroll
            for (int ma = 0; ma < 4; ma++) {
                uint32_t a[4];
                ldsm4(a, Ab + (uint32_t)(ma * 16) * GSTB + ks * 32);
                #pragma unroll
                for (int nb = 0; nb < 2; nb++) {
                    mma_f16(acc[ma][nb * 2],     a, bm[nb][0], bm[nb][1]);
                    mma_f16(acc[ma][nb * 2 + 1], a, bm[nb][2], bm[nb][3]);
                }
            }
        }
    }

    __half* dsth = (z == 0) ? g_Qh : (z == 1) ? g_Kh : g_Vh;
    #pragma unroll
    for (int ma = 0; ma < 4; ma++) {
        #pragma unroll
        for (int na = 0; na < 4; na++) {
            const int m = m0 + wm * 64 + ma * 16 + (lane >> 2);
            const int n = n0 + wn * 32 + na * 8 + 2 * (lane & 3);
            const float* a = acc[ma][na];
            const int bb = m / Nseq;
            const int nn = m - bb * Nseq;
            const int h  = n >> 6;
            const int hd = n & 63;
            __half* base = dsth + (((size_t)bb * H_ + h) * Nseq + nn) * HD_ + hd;
            *(__half2*)base              = __floats2half2_rn(a[0], a[1]);
            *(__half2*)(base + 8 * HD_)  = __floats2half2_rn(a[2], a[3]);
        }
    }
}

// =======================================================================
// Wo GEMM, pure fp16 (R14-proven): A = AO fp16 (g_AO bytes), W = Wo fp16
// (g_Kh). fp32 output.
// =======================================================================
__global__ __launch_bounds__(256, 2)
void gemm_wo_h(float* __restrict__ out)
{
    extern __shared__ char smem[];
    const uint32_t sb = smem_u32(smem);

    const int tid  = threadIdx.x;
    const int lane = tid & 31;
    const int wid  = tid >> 5;
    const int wm   = wid >> 2;
    const int wn   = wid & 3;
    const int m0   = blockIdx.y * 128;
    const int n0   = blockIdx.x * 128;

    const __half* Ag = (const __half*)g_AO + (size_t)m0 * 512;
    const __half* Wg = g_Kh + (size_t)n0 * 512;

    const uint32_t a_l = (uint32_t)(lane & 15) * GSTB + (uint32_t)(lane >> 4) * 16;
    const uint32_t b_l = (uint32_t)((lane & 7) + ((lane >> 4) & 1) * 8) * GSTB
                       + (uint32_t)((lane >> 3) & 1) * 16;

    float acc[4][4][4];
    #pragma unroll
    for (int i = 0; i < 4; i++)
        #pragma unroll
        for (int j = 0; j < 4; j++)
            #pragma unroll
            for (int r = 0; r < 4; r++) acc[i][j][r] = 0.f;

    auto load_ab = [&](int kt, int st) {
        const uint32_t SA = sb + (uint32_t)st * GSTG;
        const uint32_t SW = SA + GTILE;
        #pragma unroll
        for (int i = 0; i < 4; i++) {
            int idx = tid + i * 256;
            int r = idx >> 3, sg = idx & 7;
            cp16s(SA + (uint32_t)r * GSTB + sg * 16, Ag + (size_t)r * 512 + kt * 64 + sg * 8);
            cp16s(SW + (uint32_t)r * GSTB + sg * 16, Wg + (size_t)r * 512 + kt * 64 + sg * 8);
        }
    };

    load_ab(0, 0); CP_COMMIT();
    load_ab(1, 1); CP_COMMIT();

    for (int kt = 0; kt < 8; kt++) {
        const int st = kt % 3;
        asm volatile("cp.async.wait_group 1;");
        __syncthreads();
        if (kt + 2 < 8) load_ab(kt + 2, (kt + 2) % 3);
        CP_COMMIT();

        const uint32_t Ab = sb + (uint32_t)st * GSTG + (uint32_t)(wm * 64) * GSTB + a_l;
        const uint32_t Wb = sb + (uint32_t)st * GSTG + GTILE + (uint32_t)(wn * 32) * GSTB + b_l;
        #pragma unroll
        for (int ks = 0; ks < 4; ks++) {
            uint32_t bm[2][4];
            ldsm4(bm[0], Wb + ks * 32);
            ldsm4(bm[1], Wb + (uint32_t)16 * GSTB + ks * 32);
            #pragma unroll
            for (int ma = 0; ma < 4; ma++) {
                uint32_t a[4];
                ldsm4(a, Ab + (uint32_t)(ma * 16) * GSTB + ks * 32);
                #pragma unroll
                for (int nb = 0; nb < 2; nb++) {
                    mma_f16(acc[ma][nb * 2],     a, bm[nb][0], bm[nb][1]);
                    mma_f16(acc[ma][nb * 2 + 1], a, bm[nb][2], bm[nb][3]);
                }
            }
        }
    }

    #pragma unroll
    for (int ma = 0; ma < 4; ma++) {
        #pragma unroll
        for (int na = 0; na < 4; na++) {
            const int m = m0 + wm * 64 + ma * 16 + (lane >> 2);
            const int n = n0 + wn * 32 + na * 8 + 2 * (lane & 3);
            const float* a = acc[ma][na];
            *(float2*)(out + (size_t)m * 512 + n)       = make_float2(a[0], a[1]);
            *(float2*)(out + (size_t)(m + 8) * 512 + n) = make_float2(a[2], a[3]);
        }
    }
}

// =======================================================================
// fp16 flash attention. R15 deltas:
//  - bias initializes the S accumulators (the QK MMA performs the add)
//  - exp2-based softmax: exp2(s*L2E - m*L2E), FFMA+EX2 per element
// =======================================================================
#define ASTB 144
#define KVST (2 * 64 * ASTB)
#define ATT_SMEM (128 * ASTB + 4 * KVST)      // 92160 B
#define L2E_ 1.4426950408889634f

__global__ __launch_bounds__(256, 2)
void attn_f16(const float* __restrict__ pos_bias)
{
    extern __shared__ char smem[];
    const uint32_t sb  = smem_u32(smem);
    const uint32_t SQ  = sb;
    const uint32_t SKV = sb + 128 * ASTB;

    const int tid  = threadIdx.x;
    const int lane = tid & 31;
    const int wid  = tid >> 5;
    const int bx = blockIdx.x;
    const int qt = bx & 7;
    const int h  = (bx >> 3) & 7;
    const int b  = bx >> 6;
    const int mrow = wid * 16;

    const uint32_t q_l = (uint32_t)(mrow + (lane & 15)) * ASTB + (uint32_t)(lane >> 4) * 16;
    const uint32_t k_l = (uint32_t)((lane & 7) + ((lane >> 4) & 1) * 8) * ASTB
                       + (uint32_t)((lane >> 3) & 1) * 16;
    const uint32_t v_l = (uint32_t)((lane & 7) + ((lane >> 3) & 1) * 8) * ASTB
                       + (uint32_t)((lane >> 4) & 1) * 16;

    const __half* Qg  = g_Qh + (((size_t)b * H_ + h) * NQ_ + (size_t)qt * 128) * HD_;
    const __half* Kg0 = g_Kh + (((size_t)b * H_ + h) * NKV_) * HD_;
    const __half* Vg0 = g_Vh + (((size_t)b * H_ + h) * NKV_) * HD_;

    auto load_kv = [&](int tt, int st) {
        const uint32_t SK = SKV + (uint32_t)st * KVST;
        const uint32_t SV = SK + 9216;
        const __half* Kg = Kg0 + (size_t)tt * 64 * HD_;
        const __half* Vg = Vg0 + (size_t)tt * 64 * HD_;
        #pragma unroll
        for (int i = 0; i < 2; i++) {
            int idx = tid + i * 256, r = idx >> 3, s = idx & 7;
            cp16s(SK + (uint32_t)r * ASTB + s * 16, Kg + (size_t)r * HD_ + s * 8);
            cp16s(SV + (uint32_t)r * ASTB + s * 16, Vg + (size_t)r * HD_ + s * 8);
        }
    };

    #pragma unroll
    for (int i = 0; i < 4; i++) {
        int idx = tid + i * 256, r = idx >> 3, s = idx & 7;
        cp16s(SQ + (uint32_t)r * ASTB + s * 16, Qg + (size_t)r * HD_ + s * 8);
    }
    load_kv(0, 0); CP_COMMIT();
    load_kv(1, 1); CP_COMMIT();
    load_kv(2, 2); CP_COMMIT();

    float o[8][4];
    #pragma unroll
    for (int na = 0; na < 8; na++)
        #pragma unroll
        for (int r = 0; r < 4; r++) o[na][r] = 0.f;
    float m_0 = -1e30f, m_1 = -1e30f, l0 = 0.f, l1 = 0.f;

    const float* bias_r0 = pos_bias
        + ((size_t)h * NQ_ + (size_t)qt * 128 + mrow + (lane >> 2)) * NKV_ + 2 * (lane & 3);

    float2 blo[8], bhi[8];
    #pragma unroll
    for (int na = 0; na < 8; na++) {
        blo[na] = *(const float2*)(bias_r0 + na * 8);
        bhi[na] = *(const float2*)(bias_r0 + (size_t)8 * NKV_ + na * 8);
    }

    for (int t = 0; t < 32; t++) {
        const uint32_t K = SKV + (uint32_t)(t & 3) * KVST;
        const uint32_t V = K + 9216;

        asm volatile("cp.async.wait_group 2;");
        __syncthreads();

        if (t + 3 < 32) load_kv(t + 3, (t + 3) & 3);
        CP_COMMIT();

        // ---- S = bias + Q @ K^T  (bias rides in the accumulator) ----
        float s[8][4];
        #pragma unroll
        for (int na = 0; na < 8; na++) {
            s[na][0] = blo[na].x; s[na][1] = blo[na].y;
            s[na][2] = bhi[na].x; s[na][3] = bhi[na].y;
        }

        #pragma unroll
        for (int ks = 0; ks < 4; ks++) {
            uint32_t a[4];
            ldsm4(a, SQ + q_l + ks * 32);
            #pragma unroll
            for (int nb = 0; nb < 4; nb++) {
                uint32_t bm[4];
                ldsm4(bm, K + k_l + (uint32_t)(nb * 16) * ASTB + ks * 32);
                mma_f16(s[nb * 2],     a, bm[0], bm[1]);
                mma_f16(s[nb * 2 + 1], a, bm[2], bm[3]);
            }
        }

        // ---- online softmax (exp2 form) ----
        float rmax0 = -1e30f, rmax1 = -1e30f;
        #pragma unroll
        for (int na = 0; na < 8; na++) {
            rmax0 = fmaxf(rmax0, fmaxf(s[na][0], s[na][1]));
            rmax1 = fmaxf(rmax1, fmaxf(s[na][2], s[na][3]));
        }
        rmax0 = fmaxf(rmax0, __shfl_xor_sync(0xffffffffu, rmax0, 1));
        rmax0 = fmaxf(rmax0, __shfl_xor_sync(0xffffffffu, rmax0, 2));
        rmax1 = fmaxf(rmax1, __shfl_xor_sync(0xffffffffu, rmax1, 1));
        rmax1 = fmaxf(rmax1, __shfl_xor_sync(0xffffffffu, rmax1, 2));

        const float mn0 = fmaxf(m_0, rmax0);
        const float mn1 = fmaxf(m_1, rmax1);
        const float mn0L = mn0 * L2E_;
        const float mn1L = mn1 * L2E_;
        const float al0 = exp2f(m_0 * L2E_ - mn0L);
        const float al1 = exp2f(m_1 * L2E_ - mn1L);
        m_0 = mn0; m_1 = mn1;

        float rs0 = 0.f, rs1 = 0.f;
        #pragma unroll
        for (int na = 0; na < 8; na++) {
            s[na][0] = exp2f(s[na][0] * L2E_ - mn0L); rs0 += s[na][0];
            s[na][1] = exp2f(s[na][1] * L2E_ - mn0L); rs0 += s[na][1];
            s[na][2] = exp2f(s[na][2] * L2E_ - mn1L); rs1 += s[na][2];
            s[na][3] = exp2f(s[na][3] * L2E_ - mn1L); rs1 += s[na][3];
        }
        l0 = l0 * al0 + rs0;
        l1 = l1 * al1 + rs1;

        // ---- pack P ----
        uint32_t pp[4][4];
        #pragma unroll
        for (int ks = 0; ks < 4; ks++) {
            pp[ks][0] = h2pack(s[2*ks][0],   s[2*ks][1]);
            pp[ks][1] = h2pack(s[2*ks][2],   s[2*ks][3]);
            pp[ks][2] = h2pack(s[2*ks+1][0], s[2*ks+1][1]);
            pp[ks][3] = h2pack(s[2*ks+1][2], s[2*ks+1][3]);
        }

        // ---- prefetch bias for t+1 ----
        if (t < 31) {
            const float* bb = bias_r0 + (size_t)(t + 1) * 64;
            #pragma unroll
            for (int na = 0; na < 8; na++) {
                blo[na] = *(const float2*)(bb + na * 8);
                bhi[na] = *(const float2*)(bb + (size_t)8 * NKV_ + na * 8);
            }
        }

        // ---- conditional O rescale ----
        bool need = (al0 != 1.0f) || (al1 != 1.0f);
        if (__any_sync(0xffffffffu, need)) {
            #pragma unroll
            for (int na = 0; na < 8; na++) {
                o[na][0] *= al0; o[na][1] *= al0;
                o[na][2] *= al1; o[na][3] *= al1;
            }
        }

        // ---- O += P @ V ----
        #pragma unroll
        for (int ks = 0; ks < 4; ks++) {
            #pragma unroll
            for (int nb = 0; nb < 4; nb++) {
                uint32_t bm[4];
                ldsm4t(bm, V + v_l + (uint32_t)(ks * 16) * ASTB + nb * 32);
                mma_f16(o[nb * 2],     pp[ks], bm[0], bm[1]);
                mma_f16(o[nb * 2 + 1], pp[ks], bm[2], bm[3]);
            }
        }
    }

    l0 += __shfl_xor_sync(0xffffffffu, l0, 1);
    l0 += __shfl_xor_sync(0xffffffffu, l0, 2);
    l1 += __shfl_xor_sync(0xffffffffu, l1, 1);
    l1 += __shfl_xor_sync(0xffffffffu, l1, 2);
    const float inv0 = 1.0f / l0;
    const float inv1 = 1.0f / l1;

    // epilogue: fp16 AO into g_AO bytes
    __half* aoh = (__half*)g_AO;
    const size_t r0 = (size_t)b * NQ_ + (size_t)qt * 128 + mrow + (lane >> 2);
    #pragma unroll
    for (int na = 0; na < 8; na++) {
        const int col = h * HD_ + na * 8 + 2 * (lane & 3);
        *(__half2*)(aoh + r0 * D_ + col) =
            __floats2half2_rn(o[na][0] * inv0, o[na][1] * inv0);
        *(__half2*)(aoh + (r0 + 8) * D_ + col) =
            __floats2half2_rn(o[na][2] * inv1, o[na][3] * inv1);
    }
}

// =======================================================================
// launch — stream-ordered aliasing (unchanged from R14):
//   x_fp16 in g_Vh, enc_fp16 in g_AO, Wq/Wk/Wv fp16 in d_out,
//   AO fp16 in g_AO, Wo fp16 in g_Kh (post-attention).
// =======================================================================
extern "C" void kernel_launch(void* const* d_in, const int* in_sizes, int n_in,
                              void* d_out, int out_size)
{
    const float* x        = (const float*)d_in[0];
    const float* enc      = (const float*)d_in[1];
    const float* pos_bias = (const float*)d_in[2];
    const float* Wq       = (const float*)d_in[3];
    const float* Wk       = (const float*)d_in[4];
    const float* Wv       = (const float*)d_in[5];
    const float* Wo       = (const float*)d_in[6];
    float* out = (float*)d_out;
    __half* wh = (__half*)d_out;

    cudaFuncSetAttribute(gemm_qkv,  cudaFuncAttributeMaxDynamicSharedMemorySize, GEMM_SMEM);
    cudaFuncSetAttribute(gemm_wo_h, cudaFuncAttributeMaxDynamicSharedMemorySize, GEMM_SMEM);
    cudaFuncSetAttribute(attn_f16,  cudaFuncAttributeMaxDynamicSharedMemorySize, ATT_SMEM);

    cvt_all<<<(CVT_TOTAL / 8 + 255) / 256, 256>>>(x, enc, Wq, Wk, Wv, wh);
    gemm_qkv<<<dim3(4, 128, 3), 256, GEMM_SMEM>>>(wh);
    attn_f16<<<B_ * H_ * (NQ_ / 128), 256, ATT_SMEM>>>(pos_bias);
    cvt_wo<<<(NW_ / 8 + 255) / 256, 256>>>(Wo);
    gemm_wo_h<<<dim3(4, 64), 256, GEMM_SMEM>>>(out);
}